// round 11
// baseline (speedup 1.0000x reference)
#include <cuda_runtime.h>

#define CCH 32
#define HH 128
#define WW 128
#define NPTS 262144
#define PLANE_ELEMS (HH * WW * CCH)

typedef unsigned long long ull;

// Transposed triplanes: (plane, y, x, c) -- 6.3 MB, L2-resident
__device__ float g_tp[3 * PLANE_ELEMS];
// Sampled features in (b, c, pos) layout; MLP row r reads flat [r*32 .. r*32+31]
__device__ float g_sampled[4 * CCH * NPTS];   // 134 MB

// ---------------------------------------------------------------------------
// packed f32x2 helpers
// ---------------------------------------------------------------------------
__device__ __forceinline__ ull fma2(ull a, ull b, ull c) {
    ull d;
    asm("fma.rn.f32x2 %0, %1, %2, %3;" : "=l"(d) : "l"(a), "l"(b), "l"(c));
    return d;
}
__device__ __forceinline__ ull pack2(float lo, float hi) {
    ull r;
    asm("mov.b64 %0, {%1, %2};" : "=l"(r) : "f"(lo), "f"(hi));
    return r;
}
__device__ __forceinline__ void unpack2(ull v, float& lo, float& hi) {
    asm("mov.b64 {%0, %1}, %2;" : "=f"(lo), "=f"(hi) : "l"(v));
}

// ---------------------------------------------------------------------------
// K1: transpose (3*C, H, W) -> (3, H, W, C)
// ---------------------------------------------------------------------------
__global__ void transpose_kernel(const float* __restrict__ tri) {
    int t = blockIdx.x * blockDim.x + threadIdx.x;
    if (t >= 3 * HH * WW) return;
    int p  = t / (HH * WW);
    int yx = t - p * (HH * WW);
    const float* src = tri + (size_t)p * CCH * HH * WW + yx;
    float v[CCH];
#pragma unroll
    for (int c = 0; c < CCH; c++) v[c] = src[(size_t)c * HH * WW];
    float4* dst = (float4*)(g_tp + (size_t)t * CCH);
#pragma unroll
    for (int k = 0; k < 8; k++)
        dst[k] = make_float4(v[4*k], v[4*k+1], v[4*k+2], v[4*k+3]);
}

// ---------------------------------------------------------------------------
// K2: cooperative sampler (unchanged from R7, proven ~50us)
// ---------------------------------------------------------------------------
__device__ __forceinline__ void sample_plane_c(const float* __restrict__ plane,
                                               float gx, float gy, int s,
                                               float4& acc) {
    float x = (gx + 1.0f) * 0.5f * (WW - 1);
    float y = (gy + 1.0f) * 0.5f * (HH - 1);
    float x0f = floorf(x), y0f = floorf(y);
    float wx = x - x0f,   wy = y - y0f;
    int x0 = (int)x0f, y0 = (int)y0f;
    int x1 = x0 + 1,   y1 = y0 + 1;

    float vxa = (x0 >= 0 && x0 < WW) ? 1.0f : 0.0f;
    float vxb = (x1 >= 0 && x1 < WW) ? 1.0f : 0.0f;
    float vya = (y0 >= 0 && y0 < HH) ? 1.0f : 0.0f;
    float vyb = (y1 >= 0 && y1 < HH) ? 1.0f : 0.0f;

    int xa = min(max(x0, 0), WW - 1);
    int xb = min(max(x1, 0), WW - 1);
    int ya = min(max(y0, 0), HH - 1);
    int yb = min(max(y1, 0), HH - 1);

    float wxs[2] = {(1.0f - wx) * vxa, wx * vxb};
    float wys[2] = {(1.0f - wy) * vya, wy * vyb};
    int   xi[2]  = {xa, xb};
    int   yi[2]  = {ya, yb};

#pragma unroll
    for (int cy = 0; cy < 2; cy++) {
#pragma unroll
        for (int cx = 0; cx < 2; cx++) {
            float w = wxs[cx] * wys[cy];
            float4 v = __ldg((const float4*)(plane +
                         (size_t)(yi[cy] * WW + xi[cx]) * CCH) + s);
            acc.x = fmaf(w, v.x, acc.x);
            acc.y = fmaf(w, v.y, acc.y);
            acc.z = fmaf(w, v.z, acc.z);
            acc.w = fmaf(w, v.w, acc.w);
        }
    }
}

__global__ void __launch_bounds__(256)
sample_kernel(const float* __restrict__ coords) {
    __shared__ float st[32 * 33];
    int tid = threadIdx.x;
    int pl  = tid >> 3;
    int s   = tid & 7;
    int pbase = blockIdx.x * 32;
    int p = pbase + pl;

    float gx = __ldg(coords + 3 * p + 0);
    float gy = __ldg(coords + 3 * p + 1);
    float gz = __ldg(coords + 3 * p + 2);

    float4 acc = make_float4(0.0f, 0.0f, 0.0f, 0.0f);
    // split order: plane0 = feat_xy, plane1 = feat_yz, plane2 = feat_xz
    sample_plane_c(g_tp,                   gx, gy, s, acc);   // feat_xy(x, y)
    sample_plane_c(g_tp + 2 * PLANE_ELEMS, gx, gz, s, acc);   // feat_xz(x, z)
    sample_plane_c(g_tp +     PLANE_ELEMS, gy, gz, s, acc);   // feat_yz(y, z)

    float* row = st + pl * 33 + 4 * s;
    row[0] = acc.x; row[1] = acc.y; row[2] = acc.z; row[3] = acc.w;
    __syncthreads();

    int b       = pbase >> 18;
    int posBase = pbase & (NPTS - 1);
    float* outb = g_sampled + (size_t)b * CCH * NPTS + posBase;
#pragma unroll
    for (int i = 0; i < 4; i++) {
        int idx = tid + 256 * i;
        int c = idx >> 5;
        int q = idx & 31;
        outb[(size_t)c * NPTS + q] = st[q * 33 + c];
    }
}

// ---------------------------------------------------------------------------
// K3: tiled MLP 32 -> 128 -> 128 -> 4.
// R7 geometry (256 thr, thread tile 4 rows x 16 cols, 2 warps/SMSP — best
// measured) + R10 pipelining (double-buffered feats, register prefetch,
// 3 syncs/tile).
// ---------------------------------------------------------------------------
#define NROWS_TILE 128
#define FT_STRIDE  132
#define OFF_W1T 0                   // 16384
#define OFF_W0T 16384               // 4096
#define OFF_W2  20480               // 512
#define OFF_B0  20992               // 128
#define OFF_B1  21120               // 128
#define OFF_B2  21248               // 16
#define OFF_FT0 21264               // 32*132 = 4224
#define OFF_FT1 25488               // 4224
#define OFF_H0  29712               // 16384
#define OFF_RED 46096               // 8*128*4 = 4096
#define SMEM_FLOATS 50192           // ~201 KB

__global__ void __launch_bounds__(256, 1)
mlp_kernel(const float* __restrict__ w0, const float* __restrict__ b0,
           const float* __restrict__ w1, const float* __restrict__ b1,
           const float* __restrict__ w2, const float* __restrict__ b2,
           float* __restrict__ out, int total) {
    extern __shared__ float smem[];
    float* s_w1t = smem + OFF_W1T;
    float* s_w0t = smem + OFF_W0T;
    float* s_w2  = smem + OFF_W2;
    float* s_b0  = smem + OFF_B0;
    float* s_b1  = smem + OFF_B1;
    float* s_b2  = smem + OFF_B2;
    float* s_h0  = smem + OFF_H0;
    float* s_red = smem + OFF_RED;
    float* s_ftb[2] = { smem + OFF_FT0, smem + OFF_FT1 };

    int tid = threadIdx.x;
    for (int i = tid; i < 16384; i += 256) s_w1t[i] = w1[(i & 127) * 128 + (i >> 7)];
    for (int i = tid; i < 4096;  i += 256) s_w0t[i] = w0[(i & 127) * 32  + (i >> 7)];
    for (int i = tid; i < 512;   i += 256) s_w2[i] = w2[i];
    if (tid < 128) { s_b0[tid] = b0[tid]; s_b1[tid] = b1[tid]; }
    if (tid < 4)   { s_b2[tid] = b2[tid]; }
    __syncthreads();   // weights/biases visible before binit + first staging

    int lane = tid & 31;
    int cg   = tid >> 5;          // col group 0..7 (16 cols each)
    int c0   = cg * 16;
    int r0   = 4 * lane;

    // staging map: 2 threads per row, 16 k each
    int srow = tid >> 1;
    int sk0  = (tid & 1) * 16;

    int ntiles = total / NROWS_TILE;
    int tile0  = blockIdx.x;
    int buf = 0;

    // stage first tile's feats
    if (tile0 < ntiles) {
        const float4* src =
            (const float4*)(g_sampled + (size_t)(tile0 * NROWS_TILE + srow) * 32 + sk0);
        float4 v0 = src[0], v1 = src[1], v2 = src[2], v3 = src[3];
        float* ft = s_ftb[0];
        ft[(sk0+ 0)*FT_STRIDE + srow] = v0.x;
        ft[(sk0+ 1)*FT_STRIDE + srow] = v0.y;
        ft[(sk0+ 2)*FT_STRIDE + srow] = v0.z;
        ft[(sk0+ 3)*FT_STRIDE + srow] = v0.w;
        ft[(sk0+ 4)*FT_STRIDE + srow] = v1.x;
        ft[(sk0+ 5)*FT_STRIDE + srow] = v1.y;
        ft[(sk0+ 6)*FT_STRIDE + srow] = v1.z;
        ft[(sk0+ 7)*FT_STRIDE + srow] = v1.w;
        ft[(sk0+ 8)*FT_STRIDE + srow] = v2.x;
        ft[(sk0+ 9)*FT_STRIDE + srow] = v2.y;
        ft[(sk0+10)*FT_STRIDE + srow] = v2.z;
        ft[(sk0+11)*FT_STRIDE + srow] = v2.w;
        ft[(sk0+12)*FT_STRIDE + srow] = v3.x;
        ft[(sk0+13)*FT_STRIDE + srow] = v3.y;
        ft[(sk0+14)*FT_STRIDE + srow] = v3.z;
        ft[(sk0+15)*FT_STRIDE + srow] = v3.w;
    }

    ull binit[8];
    {
        const ulonglong2* b1v = (const ulonglong2*)(s_b1 + c0);
#pragma unroll
        for (int i = 0; i < 4; i++) {
            ulonglong2 v = b1v[i];
            binit[2*i]   = v.x;
            binit[2*i+1] = v.y;
        }
    }

    for (int tile = tile0; tile < ntiles; tile += gridDim.x) {
        int rowBase = tile * NROWS_TILE;
        __syncthreads();   // staged feats visible; s_red consumed; s_h0 free

        const float* ft = s_ftb[buf];

        // ---- phase1: h0 partial = feats @ w0^T ----
        ull acc[4][8];
#pragma unroll
        for (int r = 0; r < 4; r++)
#pragma unroll
            for (int p = 0; p < 8; p++) acc[r][p] = 0ull;

#pragma unroll 4
        for (int k = 0; k < 32; k++) {
            float4 a = *(const float4*)(ft + k*FT_STRIDE + r0);
            ull a0 = pack2(a.x, a.x), a1 = pack2(a.y, a.y);
            ull a2 = pack2(a.z, a.z), a3 = pack2(a.w, a.w);
            const ulonglong2* wv = (const ulonglong2*)(s_w0t + k*128 + c0);
#pragma unroll
            for (int i = 0; i < 4; i++) {
                ulonglong2 w = wv[i];
                acc[0][2*i]   = fma2(a0, w.x, acc[0][2*i]);
                acc[0][2*i+1] = fma2(a0, w.y, acc[0][2*i+1]);
                acc[1][2*i]   = fma2(a1, w.x, acc[1][2*i]);
                acc[1][2*i+1] = fma2(a1, w.y, acc[1][2*i+1]);
                acc[2][2*i]   = fma2(a2, w.x, acc[2][2*i]);
                acc[2][2*i+1] = fma2(a2, w.y, acc[2][2*i+1]);
                acc[3][2*i]   = fma2(a3, w.x, acc[3][2*i]);
                acc[3][2*i+1] = fma2(a3, w.y, acc[3][2*i+1]);
            }
        }

        // ---- prefetch next tile's feats into registers (hides LDG latency) ----
        int nextTile = tile + gridDim.x;
        float4 pv0, pv1, pv2, pv3;
        bool havePrefetch = (nextTile < ntiles);
        if (havePrefetch) {
            const float4* src =
                (const float4*)(g_sampled + (size_t)(nextTile * NROWS_TILE + srow) * 32 + sk0);
            pv0 = src[0]; pv1 = src[1]; pv2 = src[2]; pv3 = src[3];
        }

        // ---- epilogue1: bias + relu, store transposed to s_h0[c*128 + row] ----
#pragma unroll
        for (int p = 0; p < 8; p++) {
            int c = c0 + 2*p;
            float blo = s_b0[c], bhi = s_b0[c+1];
            float lo[4], hi[4];
#pragma unroll
            for (int r = 0; r < 4; r++) {
                float l, h;
                unpack2(acc[r][p], l, h);
                lo[r] = fmaxf(l + blo, 0.0f);
                hi[r] = fmaxf(h + bhi, 0.0f);
            }
            *(float4*)(s_h0 + c*128 + r0)     = make_float4(lo[0], lo[1], lo[2], lo[3]);
            *(float4*)(s_h0 + (c+1)*128 + r0) = make_float4(hi[0], hi[1], hi[2], hi[3]);
        }

        // ---- store prefetched feats into the other buffer ----
        if (havePrefetch) {
            float* ftn = s_ftb[buf ^ 1];
            ftn[(sk0+ 0)*FT_STRIDE + srow] = pv0.x;
            ftn[(sk0+ 1)*FT_STRIDE + srow] = pv0.y;
            ftn[(sk0+ 2)*FT_STRIDE + srow] = pv0.z;
            ftn[(sk0+ 3)*FT_STRIDE + srow] = pv0.w;
            ftn[(sk0+ 4)*FT_STRIDE + srow] = pv1.x;
            ftn[(sk0+ 5)*FT_STRIDE + srow] = pv1.y;
            ftn[(sk0+ 6)*FT_STRIDE + srow] = pv1.z;
            ftn[(sk0+ 7)*FT_STRIDE + srow] = pv1.w;
            ftn[(sk0+ 8)*FT_STRIDE + srow] = pv2.x;
            ftn[(sk0+ 9)*FT_STRIDE + srow] = pv2.y;
            ftn[(sk0+10)*FT_STRIDE + srow] = pv2.z;
            ftn[(sk0+11)*FT_STRIDE + srow] = pv2.w;
            ftn[(sk0+12)*FT_STRIDE + srow] = pv3.x;
            ftn[(sk0+13)*FT_STRIDE + srow] = pv3.y;
            ftn[(sk0+14)*FT_STRIDE + srow] = pv3.z;
            ftn[(sk0+15)*FT_STRIDE + srow] = pv3.w;
        }
        __syncthreads();   // s_h0 ready

        // ---- phase2: h1 = relu(h0 @ w1^T + b1) ----
        ull acc1[4][8];
#pragma unroll
        for (int r = 0; r < 4; r++)
#pragma unroll
            for (int p = 0; p < 8; p++) acc1[r][p] = binit[p];

#pragma unroll 4
        for (int k = 0; k < 128; k++) {
            float4 a = *(const float4*)(s_h0 + k*128 + r0);
            ull a0 = pack2(a.x, a.x), a1 = pack2(a.y, a.y);
            ull a2 = pack2(a.z, a.z), a3 = pack2(a.w, a.w);
            const ulonglong2* wv = (const ulonglong2*)(s_w1t + k*128 + c0);
#pragma unroll
            for (int i = 0; i < 4; i++) {
                ulonglong2 w = wv[i];
                acc1[0][2*i]   = fma2(a0, w.x, acc1[0][2*i]);
                acc1[0][2*i+1] = fma2(a0, w.y, acc1[0][2*i+1]);
                acc1[1][2*i]   = fma2(a1, w.x, acc1[1][2*i]);
                acc1[1][2*i+1] = fma2(a1, w.y, acc1[1][2*i+1]);
                acc1[2][2*i]   = fma2(a2, w.x, acc1[2][2*i]);
                acc1[2][2*i+1] = fma2(a2, w.y, acc1[2][2*i+1]);
                acc1[3][2*i]   = fma2(a3, w.x, acc1[3][2*i]);
                acc1[3][2*i+1] = fma2(a3, w.y, acc1[3][2*i+1]);
            }
        }

        // relu h1 (repack)
#pragma unroll
        for (int r = 0; r < 4; r++)
#pragma unroll
            for (int p = 0; p < 8; p++) {
                float l, h;
                unpack2(acc1[r][p], l, h);
                acc1[r][p] = pack2(fmaxf(l, 0.0f), fmaxf(h, 0.0f));
            }

        // ---- phase3: partial layer2 over this warp's 16 cols ----
        float part[4][4];
#pragma unroll
        for (int kk = 0; kk < 4; kk++) {
            const ulonglong2* w2v = (const ulonglong2*)(s_w2 + kk*128 + c0);
            ull wp[8];
#pragma unroll
            for (int i = 0; i < 4; i++) {
                ulonglong2 v = w2v[i];
                wp[2*i] = v.x; wp[2*i+1] = v.y;
            }
#pragma unroll
            for (int r = 0; r < 4; r++) {
                ull s0 = 0ull, s1 = 0ull;
#pragma unroll
                for (int p = 0; p < 4; p++) {
                    s0 = fma2(acc1[r][2*p],   wp[2*p],   s0);
                    s1 = fma2(acc1[r][2*p+1], wp[2*p+1], s1);
                }
                float a, b, c, d;
                unpack2(s0, a, b);
                unpack2(s1, c, d);
                part[r][kk] = (a + b) + (c + d);
            }
        }
#pragma unroll
        for (int r = 0; r < 4; r++)
            *(float4*)(s_red + (size_t)(cg*128 + r0 + r) * 4) =
                make_float4(part[r][0], part[r][1], part[r][2], part[r][3]);
        __syncthreads();   // s_red ready

        // ---- reduce across 8 col groups, relu, permute, store ----
        if (tid < 128) {
            float o0 = s_b2[0], o1 = s_b2[1], o2 = s_b2[2], o3 = s_b2[3];
#pragma unroll
            for (int g = 0; g < 8; g++) {
                float4 v = *(const float4*)(s_red + (size_t)(g*128 + tid) * 4);
                o0 += v.x; o1 += v.y; o2 += v.z; o3 += v.w;
            }
            o0 = fmaxf(o0, 0.0f); o1 = fmaxf(o1, 0.0f);
            o2 = fmaxf(o2, 0.0f); o3 = fmaxf(o3, 0.0f);
            // raw = concat(net[...,1:4], net[...,0:1])
            ((float4*)out)[rowBase + tid] = make_float4(o1, o2, o3, o0);
        }
        buf ^= 1;
    }
}

// ---------------------------------------------------------------------------
extern "C" void kernel_launch(void* const* d_in, const int* in_sizes, int n_in,
                              void* d_out, int out_size) {
    const float* coords = (const float*)d_in[0];
    const float* tri    = (const float*)d_in[1];
    const float* w0     = (const float*)d_in[2];
    const float* b0     = (const float*)d_in[3];
    const float* w1     = (const float*)d_in[4];
    const float* b1     = (const float*)d_in[5];
    const float* w2     = (const float*)d_in[6];
    const float* b2     = (const float*)d_in[7];
    float* out = (float*)d_out;

    int total = in_sizes[0] / 3;   // B * N points = MLP rows

    transpose_kernel<<<(3 * HH * WW + 127) / 128, 128>>>(tri);
    sample_kernel<<<total / 32, 256>>>(coords);

    int mlp_smem = SMEM_FLOATS * 4;   // ~201 KB dynamic shared
    cudaFuncSetAttribute(mlp_kernel,
                         cudaFuncAttributeMaxDynamicSharedMemorySize, mlp_smem);
    mlp_kernel<<<148, 256, mlp_smem>>>(w0, b0, w1, b1, w2, b2, out, total);
}

// round 12
// speedup vs baseline: 1.2839x; 1.2839x over previous
#include <cuda_runtime.h>
#include <cstdint>

#define CCH 32
#define HH 128
#define WW 128
#define NPTS 262144
#define PLANE_ELEMS (HH * WW * CCH)

// Transposed triplanes: (plane, y, x, c) -- 6.3 MB, L2-resident
__device__ float g_tp[3 * PLANE_ELEMS];
// Sampled features in (b, c, pos) layout; MLP row r reads flat [r*32 .. r*32+31]
__device__ float g_sampled[4 * CCH * NPTS];   // 134 MB

// ---------------------------------------------------------------------------
// tf32 helpers + mma.sync (Ampere-style; maps to fallback HMMA on sm_103a)
// ---------------------------------------------------------------------------
__device__ __forceinline__ uint32_t f32_to_tf32(float v) {
    uint32_t u;
    asm("cvt.rna.tf32.f32 %0, %1;" : "=r"(u) : "f"(v));
    return u;
}
__device__ __forceinline__ void mma8(float* d, const uint32_t* a,
                                     uint32_t b0, uint32_t b1) {
    asm volatile(
        "mma.sync.aligned.m16n8k8.row.col.f32.tf32.tf32.f32 "
        "{%0,%1,%2,%3}, {%4,%5,%6,%7}, {%8,%9}, {%0,%1,%2,%3};"
        : "+f"(d[0]), "+f"(d[1]), "+f"(d[2]), "+f"(d[3])
        : "r"(a[0]), "r"(a[1]), "r"(a[2]), "r"(a[3]), "r"(b0), "r"(b1));
}

// ---------------------------------------------------------------------------
// K1: transpose (3*C, H, W) -> (3, H, W, C)
// ---------------------------------------------------------------------------
__global__ void transpose_kernel(const float* __restrict__ tri) {
    int t = blockIdx.x * blockDim.x + threadIdx.x;
    if (t >= 3 * HH * WW) return;
    int p  = t / (HH * WW);
    int yx = t - p * (HH * WW);
    const float* src = tri + (size_t)p * CCH * HH * WW + yx;
    float v[CCH];
#pragma unroll
    for (int c = 0; c < CCH; c++) v[c] = src[(size_t)c * HH * WW];
    float4* dst = (float4*)(g_tp + (size_t)t * CCH);
#pragma unroll
    for (int k = 0; k < 8; k++)
        dst[k] = make_float4(v[4*k], v[4*k+1], v[4*k+2], v[4*k+3]);
}

// ---------------------------------------------------------------------------
// K2: cooperative sampler (unchanged from R7, proven ~50us)
// ---------------------------------------------------------------------------
__device__ __forceinline__ void sample_plane_c(const float* __restrict__ plane,
                                               float gx, float gy, int s,
                                               float4& acc) {
    float x = (gx + 1.0f) * 0.5f * (WW - 1);
    float y = (gy + 1.0f) * 0.5f * (HH - 1);
    float x0f = floorf(x), y0f = floorf(y);
    float wx = x - x0f,   wy = y - y0f;
    int x0 = (int)x0f, y0 = (int)y0f;
    int x1 = x0 + 1,   y1 = y0 + 1;

    float vxa = (x0 >= 0 && x0 < WW) ? 1.0f : 0.0f;
    float vxb = (x1 >= 0 && x1 < WW) ? 1.0f : 0.0f;
    float vya = (y0 >= 0 && y0 < HH) ? 1.0f : 0.0f;
    float vyb = (y1 >= 0 && y1 < HH) ? 1.0f : 0.0f;

    int xa = min(max(x0, 0), WW - 1);
    int xb = min(max(x1, 0), WW - 1);
    int ya = min(max(y0, 0), HH - 1);
    int yb = min(max(y1, 0), HH - 1);

    float wxs[2] = {(1.0f - wx) * vxa, wx * vxb};
    float wys[2] = {(1.0f - wy) * vya, wy * vyb};
    int   xi[2]  = {xa, xb};
    int   yi[2]  = {ya, yb};

#pragma unroll
    for (int cy = 0; cy < 2; cy++) {
#pragma unroll
        for (int cx = 0; cx < 2; cx++) {
            float w = wxs[cx] * wys[cy];
            float4 v = __ldg((const float4*)(plane +
                         (size_t)(yi[cy] * WW + xi[cx]) * CCH) + s);
            acc.x = fmaf(w, v.x, acc.x);
            acc.y = fmaf(w, v.y, acc.y);
            acc.z = fmaf(w, v.z, acc.z);
            acc.w = fmaf(w, v.w, acc.w);
        }
    }
}

__global__ void __launch_bounds__(256)
sample_kernel(const float* __restrict__ coords) {
    __shared__ float st[32 * 33];
    int tid = threadIdx.x;
    int pl  = tid >> 3;
    int s   = tid & 7;
    int pbase = blockIdx.x * 32;
    int p = pbase + pl;

    float gx = __ldg(coords + 3 * p + 0);
    float gy = __ldg(coords + 3 * p + 1);
    float gz = __ldg(coords + 3 * p + 2);

    float4 acc = make_float4(0.0f, 0.0f, 0.0f, 0.0f);
    // split order: plane0 = feat_xy, plane1 = feat_yz, plane2 = feat_xz
    sample_plane_c(g_tp,                   gx, gy, s, acc);   // feat_xy(x, y)
    sample_plane_c(g_tp + 2 * PLANE_ELEMS, gx, gz, s, acc);   // feat_xz(x, z)
    sample_plane_c(g_tp +     PLANE_ELEMS, gy, gz, s, acc);   // feat_yz(y, z)

    float* row = st + pl * 33 + 4 * s;
    row[0] = acc.x; row[1] = acc.y; row[2] = acc.z; row[3] = acc.w;
    __syncthreads();

    int b       = pbase >> 18;
    int posBase = pbase & (NPTS - 1);
    float* outb = g_sampled + (size_t)b * CCH * NPTS + posBase;
#pragma unroll
    for (int i = 0; i < 4; i++) {
        int idx = tid + 256 * i;
        int c = idx >> 5;
        int q = idx & 31;
        outb[(size_t)c * NPTS + q] = st[q * 33 + c];
    }
}

// ---------------------------------------------------------------------------
// K3: MLP 32->128->128->4 on mma.sync m16n8k8 tf32 with 3xTF32 split.
// 256 thr / 8 warps. Tile = 64 rows. Warp: stripe = wid&3 (16 rows),
// nhalf = wid>>2 (64 cols). Weights pre-split hi/lo + packed in fragment
// lane order (one LDS.64 per B-frag). Activations split on the fly.
// ---------------------------------------------------------------------------
#define RT 64
// smem float offsets
#define OFF_W1H 0          // 16*16*64 = 16384
#define OFF_W1L 16384      // 16384
#define OFF_W0H 32768      // 4*16*64 = 4096
#define OFF_W0L 36864      // 4096
#define OFF_H0  40960      // 64*132 = 8448
#define OFF_FT  49408      // 64*36  = 2304
#define OFF_W2T 51712      // 512
#define OFF_B0  52224      // 128
#define OFF_B1  52352      // 128
#define OFF_B2  52480      // 16
#define OFF_RED 52496      // 2*64*4 = 512
#define SMEM_FLOATS 53008  // ~212 KB

__global__ void __launch_bounds__(256, 1)
mlp_kernel(const float* __restrict__ w0, const float* __restrict__ b0,
           const float* __restrict__ w1, const float* __restrict__ b1,
           const float* __restrict__ w2, const float* __restrict__ b2,
           float* __restrict__ out, int total) {
    extern __shared__ float smem[];
    uint32_t* s_w1h = (uint32_t*)(smem + OFF_W1H);
    uint32_t* s_w1l = (uint32_t*)(smem + OFF_W1L);
    uint32_t* s_w0h = (uint32_t*)(smem + OFF_W0H);
    uint32_t* s_w0l = (uint32_t*)(smem + OFF_W0L);
    float* s_h0  = smem + OFF_H0;
    float* s_ft  = smem + OFF_FT;
    float* s_w2t = smem + OFF_W2T;
    float* s_b0  = smem + OFF_B0;
    float* s_b1  = smem + OFF_B1;
    float* s_b2  = smem + OFF_B2;
    float* s_red = smem + OFF_RED;

    int tid = threadIdx.x;

    // ---- pack w1 into hi/lo fragment order: B[k][n] = w1[n][k] ----
    // entry i: tile = i>>6 (kt*16+nt), lane = (i>>1)&31, half = i&1
    for (int i = tid; i < 16384; i += 256) {
        int tile = i >> 6, rem = i & 63;
        int lane = rem >> 1, half = rem & 1;
        int kt = tile >> 4, nt = tile & 15;
        int g = lane >> 2, tg4 = lane & 3;
        int k = kt * 8 + tg4 + half * 4;
        int n = nt * 8 + g;
        float v = w1[n * 128 + k];
        uint32_t h = f32_to_tf32(v);
        float l = v - __uint_as_float(h);
        s_w1h[i] = h;
        s_w1l[i] = f32_to_tf32(l);
    }
    // ---- pack w0 similarly (k = 0..31 -> 4 ktiles) ----
    for (int i = tid; i < 4096; i += 256) {
        int tile = i >> 6, rem = i & 63;
        int lane = rem >> 1, half = rem & 1;
        int kt = tile >> 4, nt = tile & 15;
        int g = lane >> 2, tg4 = lane & 3;
        int k = kt * 8 + tg4 + half * 4;
        int n = nt * 8 + g;
        float v = w0[n * 32 + k];
        uint32_t h = f32_to_tf32(v);
        float l = v - __uint_as_float(h);
        s_w0h[i] = h;
        s_w0l[i] = f32_to_tf32(l);
    }
    // w2 transposed: s_w2t[col*4 + kk] = w2[kk][col]
    for (int i = tid; i < 512; i += 256) s_w2t[i] = w2[(i & 3) * 128 + (i >> 2)];
    if (tid < 128) { s_b0[tid] = b0[tid]; s_b1[tid] = b1[tid]; }
    if (tid < 4)   s_b2[tid] = b2[tid];
    __syncthreads();

    int lane = tid & 31;
    int wid  = tid >> 5;
    int grp  = lane >> 2;        // 0..7
    int tg   = lane & 3;         // 0..3
    int stripe = wid & 3;        // row stripe (16 rows)
    int nhalf  = wid >> 2;       // col half (64 cols)
    int rbase  = stripe * 16;

    // staging map: row = tid>>2, k0 = (tid&3)*8
    int srow = tid >> 2;
    int sk0  = (tid & 3) * 8;

    int ntiles = total / RT;
    for (int tile = blockIdx.x; tile < ntiles; tile += gridDim.x) {
        int rowBase = tile * RT;

        // ---- stage feats row-major [row][k], stride 36 ----
        {
            const float4* src =
                (const float4*)(g_sampled + (size_t)(rowBase + srow) * 32 + sk0);
            float4 v0 = src[0], v1 = src[1];
            *(float4*)(s_ft + srow * 36 + sk0)     = v0;
            *(float4*)(s_ft + srow * 36 + sk0 + 4) = v1;
        }
        __syncthreads();

        // ---- layer0: acc0 = ft @ w0^T (3xTF32) ----
        float acc0[8][4];
#pragma unroll
        for (int nt = 0; nt < 8; nt++)
#pragma unroll
            for (int q = 0; q < 4; q++) acc0[nt][q] = 0.0f;

#pragma unroll
        for (int kt = 0; kt < 4; kt++) {
            float a0 = s_ft[(rbase + grp)     * 36 + kt*8 + tg];
            float a1 = s_ft[(rbase + grp + 8) * 36 + kt*8 + tg];
            float a2 = s_ft[(rbase + grp)     * 36 + kt*8 + tg + 4];
            float a3 = s_ft[(rbase + grp + 8) * 36 + kt*8 + tg + 4];
            uint32_t ah[4], al[4];
            ah[0] = f32_to_tf32(a0); al[0] = f32_to_tf32(a0 - __uint_as_float(ah[0]));
            ah[1] = f32_to_tf32(a1); al[1] = f32_to_tf32(a1 - __uint_as_float(ah[1]));
            ah[2] = f32_to_tf32(a2); al[2] = f32_to_tf32(a2 - __uint_as_float(ah[2]));
            ah[3] = f32_to_tf32(a3); al[3] = f32_to_tf32(a3 - __uint_as_float(ah[3]));
#pragma unroll
            for (int nt = 0; nt < 8; nt++) {
                int bt = kt * 16 + nhalf * 8 + nt;
                uint2 bh = *(const uint2*)(s_w0h + bt * 64 + lane * 2);
                uint2 bl = *(const uint2*)(s_w0l + bt * 64 + lane * 2);
                mma8(acc0[nt], ah, bh.x, bh.y);
                mma8(acc0[nt], al, bh.x, bh.y);
                mma8(acc0[nt], ah, bl.x, bl.y);
            }
        }

        // ---- epilogue0: h0 = relu(acc0 + b0), row-major stride 132 ----
#pragma unroll
        for (int nt = 0; nt < 8; nt++) {
            int col = nhalf * 64 + nt * 8 + 2 * tg;
            float2 bv = *(const float2*)(s_b0 + col);
            *(float2*)(s_h0 + (rbase + grp) * 132 + col) =
                make_float2(fmaxf(acc0[nt][0] + bv.x, 0.0f),
                            fmaxf(acc0[nt][1] + bv.y, 0.0f));
            *(float2*)(s_h0 + (rbase + grp + 8) * 132 + col) =
                make_float2(fmaxf(acc0[nt][2] + bv.x, 0.0f),
                            fmaxf(acc0[nt][3] + bv.y, 0.0f));
        }
        __syncthreads();

        // ---- layer1: acc1 = h0 @ w1^T (3xTF32) ----
        float acc1[8][4];
#pragma unroll
        for (int nt = 0; nt < 8; nt++)
#pragma unroll
            for (int q = 0; q < 4; q++) acc1[nt][q] = 0.0f;

#pragma unroll 4
        for (int kt = 0; kt < 16; kt++) {
            float a0 = s_h0[(rbase + grp)     * 132 + kt*8 + tg];
            float a1 = s_h0[(rbase + grp + 8) * 132 + kt*8 + tg];
            float a2 = s_h0[(rbase + grp)     * 132 + kt*8 + tg + 4];
            float a3 = s_h0[(rbase + grp + 8) * 132 + kt*8 + tg + 4];
            uint32_t ah[4], al[4];
            ah[0] = f32_to_tf32(a0); al[0] = f32_to_tf32(a0 - __uint_as_float(ah[0]));
            ah[1] = f32_to_tf32(a1); al[1] = f32_to_tf32(a1 - __uint_as_float(ah[1]));
            ah[2] = f32_to_tf32(a2); al[2] = f32_to_tf32(a2 - __uint_as_float(ah[2]));
            ah[3] = f32_to_tf32(a3); al[3] = f32_to_tf32(a3 - __uint_as_float(ah[3]));
#pragma unroll
            for (int nt = 0; nt < 8; nt++) {
                int bt = kt * 16 + nhalf * 8 + nt;
                uint2 bh = *(const uint2*)(s_w1h + bt * 64 + lane * 2);
                uint2 bl = *(const uint2*)(s_w1l + bt * 64 + lane * 2);
                mma8(acc1[nt], ah, bh.x, bh.y);
                mma8(acc1[nt], al, bh.x, bh.y);
                mma8(acc1[nt], ah, bl.x, bl.y);
            }
        }

        // ---- layer2 partials: h1 = relu(acc1 + b1); p += h1 * w2t ----
        float p0[4] = {0, 0, 0, 0};   // row rbase+grp
        float p1[4] = {0, 0, 0, 0};   // row rbase+grp+8
#pragma unroll
        for (int nt = 0; nt < 8; nt++) {
            int col = nhalf * 64 + nt * 8 + 2 * tg;
            float2 bv = *(const float2*)(s_b1 + col);
            float h00 = fmaxf(acc1[nt][0] + bv.x, 0.0f);
            float h01 = fmaxf(acc1[nt][1] + bv.y, 0.0f);
            float h10 = fmaxf(acc1[nt][2] + bv.x, 0.0f);
            float h11 = fmaxf(acc1[nt][3] + bv.y, 0.0f);
            float4 wv0 = *(const float4*)(s_w2t + col * 4);
            float4 wv1 = *(const float4*)(s_w2t + (col + 1) * 4);
            p0[0] = fmaf(h00, wv0.x, fmaf(h01, wv1.x, p0[0]));
            p0[1] = fmaf(h00, wv0.y, fmaf(h01, wv1.y, p0[1]));
            p0[2] = fmaf(h00, wv0.z, fmaf(h01, wv1.z, p0[2]));
            p0[3] = fmaf(h00, wv0.w, fmaf(h01, wv1.w, p0[3]));
            p1[0] = fmaf(h10, wv0.x, fmaf(h11, wv1.x, p1[0]));
            p1[1] = fmaf(h10, wv0.y, fmaf(h11, wv1.y, p1[1]));
            p1[2] = fmaf(h10, wv0.z, fmaf(h11, wv1.z, p1[2]));
            p1[3] = fmaf(h10, wv0.w, fmaf(h11, wv1.w, p1[3]));
        }
        // reduce across the 4 lanes of the quad (tg dimension)
#pragma unroll
        for (int off = 1; off <= 2; off <<= 1) {
#pragma unroll
            for (int q = 0; q < 4; q++) {
                p0[q] += __shfl_xor_sync(0xffffffffu, p0[q], off);
                p1[q] += __shfl_xor_sync(0xffffffffu, p1[q], off);
            }
        }
        if (tg == 0) {
            *(float4*)(s_red + (size_t)(nhalf * 64 + rbase + grp) * 4) =
                make_float4(p0[0], p0[1], p0[2], p0[3]);
            *(float4*)(s_red + (size_t)(nhalf * 64 + rbase + grp + 8) * 4) =
                make_float4(p1[0], p1[1], p1[2], p1[3]);
        }
        __syncthreads();

        // ---- final: sum two col-halves, bias, relu, permute, store ----
        if (tid < RT) {
            float4 v0 = *(const float4*)(s_red + (size_t)tid * 4);
            float4 v1 = *(const float4*)(s_red + (size_t)(64 + tid) * 4);
            float o0 = fmaxf(s_b2[0] + v0.x + v1.x, 0.0f);
            float o1 = fmaxf(s_b2[1] + v0.y + v1.y, 0.0f);
            float o2 = fmaxf(s_b2[2] + v0.z + v1.z, 0.0f);
            float o3 = fmaxf(s_b2[3] + v0.w + v1.w, 0.0f);
            // raw = concat(net[...,1:4], net[...,0:1])
            ((float4*)out)[rowBase + tid] = make_float4(o1, o2, o3, o0);
        }
    }
}

// ---------------------------------------------------------------------------
extern "C" void kernel_launch(void* const* d_in, const int* in_sizes, int n_in,
                              void* d_out, int out_size) {
    const float* coords = (const float*)d_in[0];
    const float* tri    = (const float*)d_in[1];
    const float* w0     = (const float*)d_in[2];
    const float* b0     = (const float*)d_in[3];
    const float* w1     = (const float*)d_in[4];
    const float* b1     = (const float*)d_in[5];
    const float* w2     = (const float*)d_in[6];
    const float* b2     = (const float*)d_in[7];
    float* out = (float*)d_out;

    int total = in_sizes[0] / 3;   // B * N points = MLP rows

    transpose_kernel<<<(3 * HH * WW + 127) / 128, 128>>>(tri);
    sample_kernel<<<total / 32, 256>>>(coords);

    int mlp_smem = SMEM_FLOATS * 4;   // ~212 KB dynamic shared
    cudaFuncSetAttribute(mlp_kernel,
                         cudaFuncAttributeMaxDynamicSharedMemorySize, mlp_smem);
    mlp_kernel<<<148, 256, mlp_smem>>>(w0, b0, w1, b1, w2, b2, out, total);
}

// round 13
// speedup vs baseline: 1.9259x; 1.5000x over previous
#include <cuda_runtime.h>
#include <cstdint>

#define CCH 32
#define HH 128
#define WW 128
#define NPTS 262144
#define PLANE_ELEMS (HH * WW * CCH)

// Transposed triplanes: (plane, y, x, c) -- 6.3 MB, L2-resident
__device__ float g_tp[3 * PLANE_ELEMS];
// Sampled features in (b, c, pos) layout; MLP row r reads flat [r*32 .. r*32+31]
__device__ float g_sampled[4 * CCH * NPTS];   // 134 MB

// ---------------------------------------------------------------------------
// bf16 helpers + mma.sync m16n8k16 (fallback HMMA on sm_103a)
// ---------------------------------------------------------------------------
__device__ __forceinline__ void mma16(float* d, const uint32_t* a,
                                      uint32_t b0, uint32_t b1) {
    asm volatile(
        "mma.sync.aligned.m16n8k16.row.col.f32.bf16.bf16.f32 "
        "{%0,%1,%2,%3}, {%4,%5,%6,%7}, {%8,%9}, {%0,%1,%2,%3};"
        : "+f"(d[0]), "+f"(d[1]), "+f"(d[2]), "+f"(d[3])
        : "r"(a[0]), "r"(a[1]), "r"(a[2]), "r"(a[3]), "r"(b0), "r"(b1));
}

// split (v0,v1) into packed bf16x2 hi + bf16x2 residual-lo ({lo16=v0, hi16=v1})
__device__ __forceinline__ void split_pack(float v0, float v1,
                                           uint32_t& hi, uint32_t& lo) {
    uint32_t h;
    asm("cvt.rn.satfinite.bf16x2.f32 %0, %1, %2;" : "=r"(h) : "f"(v1), "f"(v0));
    float h0 = __uint_as_float(h << 16);
    float h1 = __uint_as_float(h & 0xffff0000u);
    float l0 = v0 - h0, l1 = v1 - h1;
    asm("cvt.rn.satfinite.bf16x2.f32 %0, %1, %2;" : "=r"(lo) : "f"(l1), "f"(l0));
    hi = h;
}

// ---------------------------------------------------------------------------
// K1: transpose (3*C, H, W) -> (3, H, W, C)
// ---------------------------------------------------------------------------
__global__ void transpose_kernel(const float* __restrict__ tri) {
    int t = blockIdx.x * blockDim.x + threadIdx.x;
    if (t >= 3 * HH * WW) return;
    int p  = t / (HH * WW);
    int yx = t - p * (HH * WW);
    const float* src = tri + (size_t)p * CCH * HH * WW + yx;
    float v[CCH];
#pragma unroll
    for (int c = 0; c < CCH; c++) v[c] = src[(size_t)c * HH * WW];
    float4* dst = (float4*)(g_tp + (size_t)t * CCH);
#pragma unroll
    for (int k = 0; k < 8; k++)
        dst[k] = make_float4(v[4*k], v[4*k+1], v[4*k+2], v[4*k+3]);
}

// ---------------------------------------------------------------------------
// K2: cooperative sampler (unchanged from R7, proven ~50us)
// ---------------------------------------------------------------------------
__device__ __forceinline__ void sample_plane_c(const float* __restrict__ plane,
                                               float gx, float gy, int s,
                                               float4& acc) {
    float x = (gx + 1.0f) * 0.5f * (WW - 1);
    float y = (gy + 1.0f) * 0.5f * (HH - 1);
    float x0f = floorf(x), y0f = floorf(y);
    float wx = x - x0f,   wy = y - y0f;
    int x0 = (int)x0f, y0 = (int)y0f;
    int x1 = x0 + 1,   y1 = y0 + 1;

    float vxa = (x0 >= 0 && x0 < WW) ? 1.0f : 0.0f;
    float vxb = (x1 >= 0 && x1 < WW) ? 1.0f : 0.0f;
    float vya = (y0 >= 0 && y0 < HH) ? 1.0f : 0.0f;
    float vyb = (y1 >= 0 && y1 < HH) ? 1.0f : 0.0f;

    int xa = min(max(x0, 0), WW - 1);
    int xb = min(max(x1, 0), WW - 1);
    int ya = min(max(y0, 0), HH - 1);
    int yb = min(max(y1, 0), HH - 1);

    float wxs[2] = {(1.0f - wx) * vxa, wx * vxb};
    float wys[2] = {(1.0f - wy) * vya, wy * vyb};
    int   xi[2]  = {xa, xb};
    int   yi[2]  = {ya, yb};

#pragma unroll
    for (int cy = 0; cy < 2; cy++) {
#pragma unroll
        for (int cx = 0; cx < 2; cx++) {
            float w = wxs[cx] * wys[cy];
            float4 v = __ldg((const float4*)(plane +
                         (size_t)(yi[cy] * WW + xi[cx]) * CCH) + s);
            acc.x = fmaf(w, v.x, acc.x);
            acc.y = fmaf(w, v.y, acc.y);
            acc.z = fmaf(w, v.z, acc.z);
            acc.w = fmaf(w, v.w, acc.w);
        }
    }
}

__global__ void __launch_bounds__(256)
sample_kernel(const float* __restrict__ coords) {
    __shared__ float st[32 * 33];
    int tid = threadIdx.x;
    int pl  = tid >> 3;
    int s   = tid & 7;
    int pbase = blockIdx.x * 32;
    int p = pbase + pl;

    float gx = __ldg(coords + 3 * p + 0);
    float gy = __ldg(coords + 3 * p + 1);
    float gz = __ldg(coords + 3 * p + 2);

    float4 acc = make_float4(0.0f, 0.0f, 0.0f, 0.0f);
    // split order: plane0 = feat_xy, plane1 = feat_yz, plane2 = feat_xz
    sample_plane_c(g_tp,                   gx, gy, s, acc);   // feat_xy(x, y)
    sample_plane_c(g_tp + 2 * PLANE_ELEMS, gx, gz, s, acc);   // feat_xz(x, z)
    sample_plane_c(g_tp +     PLANE_ELEMS, gy, gz, s, acc);   // feat_yz(y, z)

    float* row = st + pl * 33 + 4 * s;
    row[0] = acc.x; row[1] = acc.y; row[2] = acc.z; row[3] = acc.w;
    __syncthreads();

    int b       = pbase >> 18;
    int posBase = pbase & (NPTS - 1);
    float* outb = g_sampled + (size_t)b * CCH * NPTS + posBase;
#pragma unroll
    for (int i = 0; i < 4; i++) {
        int idx = tid + 256 * i;
        int c = idx >> 5;
        int q = idx & 31;
        outb[(size_t)c * NPTS + q] = st[q * 33 + c];
    }
}

// ---------------------------------------------------------------------------
// K3: MLP 32->128->128->4 on mma.sync m16n8k16 bf16 with 3xBF16 split.
// 256 thr / 8 warps. Tile = 64 rows. stripe = wid&3 (16 rows), nhalf = wid>>2
// (64 cols). Weights AND activations pre-split/pre-packed bf16x2; mainloops
// contain only LDS + mma.
// ---------------------------------------------------------------------------
#define RT 64
#define FT_STRIDE 20     // uint32 per row (16 kp + pad) -- conflict-free
#define H0_STRIDE 68     // uint32 per row (64 kp + pad) -- conflict-free
// smem float/uint32 offsets
#define OFF_W1H 0        // 8 kt * 16 nt * 64 = 8192
#define OFF_W1L 8192     // 8192
#define OFF_W0H 16384    // 2 kt * 16 nt * 64 = 2048
#define OFF_W0L 18432    // 2048
#define OFF_FTH 20480    // 64*20 = 1280
#define OFF_FTL 21760    // 1280
#define OFF_H0H 23040    // 64*68 = 4352
#define OFF_H0L 27392    // 4352
#define OFF_W2T 31744    // 512
#define OFF_B0  32256    // 128
#define OFF_B1  32384    // 128
#define OFF_B2  32512    // 16
#define OFF_RED 32528    // 2*64*4 = 512
#define SMEM_FLOATS 33056   // ~132 KB

__global__ void __launch_bounds__(256, 1)
mlp_kernel(const float* __restrict__ w0, const float* __restrict__ b0,
           const float* __restrict__ w1, const float* __restrict__ b1,
           const float* __restrict__ w2, const float* __restrict__ b2,
           float* __restrict__ out, int total) {
    extern __shared__ float smem[];
    uint32_t* s_w1h = (uint32_t*)(smem + OFF_W1H);
    uint32_t* s_w1l = (uint32_t*)(smem + OFF_W1L);
    uint32_t* s_w0h = (uint32_t*)(smem + OFF_W0H);
    uint32_t* s_w0l = (uint32_t*)(smem + OFF_W0L);
    uint32_t* s_fth = (uint32_t*)(smem + OFF_FTH);
    uint32_t* s_ftl = (uint32_t*)(smem + OFF_FTL);
    uint32_t* s_h0h = (uint32_t*)(smem + OFF_H0H);
    uint32_t* s_h0l = (uint32_t*)(smem + OFF_H0L);
    float* s_w2t = smem + OFF_W2T;
    float* s_b0  = smem + OFF_B0;
    float* s_b1  = smem + OFF_B1;
    float* s_b2  = smem + OFF_B2;
    float* s_red = smem + OFF_RED;

    int tid = threadIdx.x;

    // ---- pack w1 hi/lo in fragment lane order ----
    // i: bt = i>>6 (kt*16+nt); rem = i&63: lane = rem>>1, half = rem&1
    // b-half holds B[k0][n], B[k0+1][n], k0 = kt*16 + 2*tg + half*8, n = nt*8+g
    for (int i = tid; i < 8192; i += 256) {
        int bt = i >> 6, rem = i & 63;
        int li = rem >> 1, half = rem & 1;
        int kt = bt >> 4, nt = bt & 15;
        int g = li >> 2, tg = li & 3;
        int k0 = kt * 16 + 2 * tg + half * 8;
        int n  = nt * 8 + g;
        uint32_t hp, lp;
        split_pack(w1[n * 128 + k0], w1[n * 128 + k0 + 1], hp, lp);
        s_w1h[i] = hp;
        s_w1l[i] = lp;
    }
    // ---- pack w0 hi/lo (2 ktiles) ----
    for (int i = tid; i < 2048; i += 256) {
        int bt = i >> 6, rem = i & 63;
        int li = rem >> 1, half = rem & 1;
        int kt = bt >> 4, nt = bt & 15;
        int g = li >> 2, tg = li & 3;
        int k0 = kt * 16 + 2 * tg + half * 8;
        int n  = nt * 8 + g;
        uint32_t hp, lp;
        split_pack(w0[n * 32 + k0], w0[n * 32 + k0 + 1], hp, lp);
        s_w0h[i] = hp;
        s_w0l[i] = lp;
    }
    // w2 transposed: s_w2t[col*4 + kk] = w2[kk][col]
    for (int i = tid; i < 512; i += 256) s_w2t[i] = w2[(i & 3) * 128 + (i >> 2)];
    if (tid < 128) { s_b0[tid] = b0[tid]; s_b1[tid] = b1[tid]; }
    if (tid < 4)   s_b2[tid] = b2[tid];
    __syncthreads();

    int lane = tid & 31;
    int wid  = tid >> 5;
    int grp  = lane >> 2;        // 0..7
    int tg   = lane & 3;         // 0..3
    int stripe = wid & 3;        // 16-row stripe
    int nhalf  = wid >> 2;       // 64-col half
    int rbase  = stripe * 16;
    int rA = rbase + grp;        // A-frag row (and rA+8)

    // staging map: row = tid>>2 (0..63), kp0 = (tid&3)*4 (4 pairs = 8 k)
    int srow = tid >> 2;
    int skp  = (tid & 3) * 4;

    int ntiles = total / RT;
    for (int tile = blockIdx.x; tile < ntiles; tile += gridDim.x) {
        int rowBase = tile * RT;

        // ---- stage feats: split+pack to bf16x2 hi/lo [row][kp] ----
        {
            const float4* src =
                (const float4*)(g_sampled + (size_t)(rowBase + srow) * 32 + skp * 2);
            float4 v0 = src[0], v1 = src[1];
            uint32_t hp, lp;
            split_pack(v0.x, v0.y, hp, lp);
            s_fth[srow * FT_STRIDE + skp]     = hp;
            s_ftl[srow * FT_STRIDE + skp]     = lp;
            split_pack(v0.z, v0.w, hp, lp);
            s_fth[srow * FT_STRIDE + skp + 1] = hp;
            s_ftl[srow * FT_STRIDE + skp + 1] = lp;
            split_pack(v1.x, v1.y, hp, lp);
            s_fth[srow * FT_STRIDE + skp + 2] = hp;
            s_ftl[srow * FT_STRIDE + skp + 2] = lp;
            split_pack(v1.z, v1.w, hp, lp);
            s_fth[srow * FT_STRIDE + skp + 3] = hp;
            s_ftl[srow * FT_STRIDE + skp + 3] = lp;
        }
        __syncthreads();

        // ---- layer0: acc0 = ft @ w0^T (3xBF16), K=32 = 2 ktiles ----
        float acc0[8][4];
#pragma unroll
        for (int nt = 0; nt < 8; nt++)
#pragma unroll
            for (int q = 0; q < 4; q++) acc0[nt][q] = 0.0f;

#pragma unroll
        for (int kt = 0; kt < 2; kt++) {
            uint32_t ah[4], al[4];
            ah[0] = s_fth[rA       * FT_STRIDE + kt*8 + tg];
            ah[1] = s_fth[(rA + 8) * FT_STRIDE + kt*8 + tg];
            ah[2] = s_fth[rA       * FT_STRIDE + kt*8 + tg + 4];
            ah[3] = s_fth[(rA + 8) * FT_STRIDE + kt*8 + tg + 4];
            al[0] = s_ftl[rA       * FT_STRIDE + kt*8 + tg];
            al[1] = s_ftl[(rA + 8) * FT_STRIDE + kt*8 + tg];
            al[2] = s_ftl[rA       * FT_STRIDE + kt*8 + tg + 4];
            al[3] = s_ftl[(rA + 8) * FT_STRIDE + kt*8 + tg + 4];
#pragma unroll
            for (int nt = 0; nt < 8; nt++) {
                int bt = kt * 16 + nhalf * 8 + nt;
                uint2 bh = *(const uint2*)(s_w0h + bt * 64 + lane * 2);
                uint2 bl = *(const uint2*)(s_w0l + bt * 64 + lane * 2);
                mma16(acc0[nt], ah, bh.x, bh.y);
                mma16(acc0[nt], al, bh.x, bh.y);
                mma16(acc0[nt], ah, bl.x, bl.y);
            }
        }

        // ---- epilogue0: h0 = relu(acc0 + b0) -> split bf16x2 -> s_h0 ----
#pragma unroll
        for (int nt = 0; nt < 8; nt++) {
            int col = nhalf * 64 + nt * 8 + 2 * tg;
            int cp  = col >> 1;                   // pair index
            float2 bv = *(const float2*)(s_b0 + col);
            uint32_t hp, lp;
            split_pack(fmaxf(acc0[nt][0] + bv.x, 0.0f),
                       fmaxf(acc0[nt][1] + bv.y, 0.0f), hp, lp);
            s_h0h[rA * H0_STRIDE + cp] = hp;
            s_h0l[rA * H0_STRIDE + cp] = lp;
            split_pack(fmaxf(acc0[nt][2] + bv.x, 0.0f),
                       fmaxf(acc0[nt][3] + bv.y, 0.0f), hp, lp);
            s_h0h[(rA + 8) * H0_STRIDE + cp] = hp;
            s_h0l[(rA + 8) * H0_STRIDE + cp] = lp;
        }
        __syncthreads();

        // ---- layer1: acc1 = h0 @ w1^T (3xBF16), K=128 = 8 ktiles ----
        float acc1[8][4];
#pragma unroll
        for (int nt = 0; nt < 8; nt++)
#pragma unroll
            for (int q = 0; q < 4; q++) acc1[nt][q] = 0.0f;

#pragma unroll
        for (int kt = 0; kt < 8; kt++) {
            uint32_t ah[4], al[4];
            ah[0] = s_h0h[rA       * H0_STRIDE + kt*8 + tg];
            ah[1] = s_h0h[(rA + 8) * H0_STRIDE + kt*8 + tg];
            ah[2] = s_h0h[rA       * H0_STRIDE + kt*8 + tg + 4];
            ah[3] = s_h0h[(rA + 8) * H0_STRIDE + kt*8 + tg + 4];
            al[0] = s_h0l[rA       * H0_STRIDE + kt*8 + tg];
            al[1] = s_h0l[(rA + 8) * H0_STRIDE + kt*8 + tg];
            al[2] = s_h0l[rA       * H0_STRIDE + kt*8 + tg + 4];
            al[3] = s_h0l[(rA + 8) * H0_STRIDE + kt*8 + tg + 4];
#pragma unroll
            for (int nt = 0; nt < 8; nt++) {
                int bt = kt * 16 + nhalf * 8 + nt;
                uint2 bh = *(const uint2*)(s_w1h + bt * 64 + lane * 2);
                uint2 bl = *(const uint2*)(s_w1l + bt * 64 + lane * 2);
                mma16(acc1[nt], ah, bh.x, bh.y);
                mma16(acc1[nt], al, bh.x, bh.y);
                mma16(acc1[nt], ah, bl.x, bl.y);
            }
        }

        // ---- layer2 partials: h1 = relu(acc1 + b1); p += h1 * w2t ----
        float p0[4] = {0, 0, 0, 0};   // row rA
        float p1[4] = {0, 0, 0, 0};   // row rA+8
#pragma unroll
        for (int nt = 0; nt < 8; nt++) {
            int col = nhalf * 64 + nt * 8 + 2 * tg;
            float2 bv = *(const float2*)(s_b1 + col);
            float h00 = fmaxf(acc1[nt][0] + bv.x, 0.0f);
            float h01 = fmaxf(acc1[nt][1] + bv.y, 0.0f);
            float h10 = fmaxf(acc1[nt][2] + bv.x, 0.0f);
            float h11 = fmaxf(acc1[nt][3] + bv.y, 0.0f);
            float4 wv0 = *(const float4*)(s_w2t + col * 4);
            float4 wv1 = *(const float4*)(s_w2t + (col + 1) * 4);
            p0[0] = fmaf(h00, wv0.x, fmaf(h01, wv1.x, p0[0]));
            p0[1] = fmaf(h00, wv0.y, fmaf(h01, wv1.y, p0[1]));
            p0[2] = fmaf(h00, wv0.z, fmaf(h01, wv1.z, p0[2]));
            p0[3] = fmaf(h00, wv0.w, fmaf(h01, wv1.w, p0[3]));
            p1[0] = fmaf(h10, wv0.x, fmaf(h11, wv1.x, p1[0]));
            p1[1] = fmaf(h10, wv0.y, fmaf(h11, wv1.y, p1[1]));
            p1[2] = fmaf(h10, wv0.z, fmaf(h11, wv1.z, p1[2]));
            p1[3] = fmaf(h10, wv0.w, fmaf(h11, wv1.w, p1[3]));
        }
        // reduce across the quad (tg dimension)
#pragma unroll
        for (int off = 1; off <= 2; off <<= 1) {
#pragma unroll
            for (int q = 0; q < 4; q++) {
                p0[q] += __shfl_xor_sync(0xffffffffu, p0[q], off);
                p1[q] += __shfl_xor_sync(0xffffffffu, p1[q], off);
            }
        }
        if (tg == 0) {
            *(float4*)(s_red + (size_t)(nhalf * 64 + rA) * 4) =
                make_float4(p0[0], p0[1], p0[2], p0[3]);
            *(float4*)(s_red + (size_t)(nhalf * 64 + rA + 8) * 4) =
                make_float4(p1[0], p1[1], p1[2], p1[3]);
        }
        __syncthreads();

        // ---- final: sum col-halves, bias, relu, permute, store ----
        if (tid < RT) {
            float4 v0 = *(const float4*)(s_red + (size_t)tid * 4);
            float4 v1 = *(const float4*)(s_red + (size_t)(64 + tid) * 4);
            float o0 = fmaxf(s_b2[0] + v0.x + v1.x, 0.0f);
            float o1 = fmaxf(s_b2[1] + v0.y + v1.y, 0.0f);
            float o2 = fmaxf(s_b2[2] + v0.z + v1.z, 0.0f);
            float o3 = fmaxf(s_b2[3] + v0.w + v1.w, 0.0f);
            // raw = concat(net[...,1:4], net[...,0:1])
            ((float4*)out)[rowBase + tid] = make_float4(o1, o2, o3, o0);
        }
    }
}

// ---------------------------------------------------------------------------
extern "C" void kernel_launch(void* const* d_in, const int* in_sizes, int n_in,
                              void* d_out, int out_size) {
    const float* coords = (const float*)d_in[0];
    const float* tri    = (const float*)d_in[1];
    const float* w0     = (const float*)d_in[2];
    const float* b0     = (const float*)d_in[3];
    const float* w1     = (const float*)d_in[4];
    const float* b1     = (const float*)d_in[5];
    const float* w2     = (const float*)d_in[6];
    const float* b2     = (const float*)d_in[7];
    float* out = (float*)d_out;

    int total = in_sizes[0] / 3;   // B * N points = MLP rows

    transpose_kernel<<<(3 * HH * WW + 127) / 128, 128>>>(tri);
    sample_kernel<<<total / 32, 256>>>(coords);

    int mlp_smem = SMEM_FLOATS * 4;   // ~132 KB dynamic shared
    cudaFuncSetAttribute(mlp_kernel,
                         cudaFuncAttributeMaxDynamicSharedMemorySize, mlp_smem);
    mlp_kernel<<<148, 256, mlp_smem>>>(w0, b0, w1, b1, w2, b2, out, total);
}

// round 14
// speedup vs baseline: 2.0715x; 1.0756x over previous
#include <cuda_runtime.h>
#include <cstdint>

#define CCH 32
#define HH 128
#define WW 128
#define NPTS 262144
#define PLANE_ELEMS (HH * WW * CCH)

// Transposed triplanes: (plane, y, x, c) -- 6.3 MB, L2-resident
__device__ float g_tp[3 * PLANE_ELEMS];
// Sampled features in (b, c, pos) layout; MLP row r reads flat [r*32 .. r*32+31]
__device__ float g_sampled[4 * CCH * NPTS];   // 134 MB

// ---------------------------------------------------------------------------
// bf16 helpers + mma.sync m16n8k16 (fallback HMMA on sm_103a)
// ---------------------------------------------------------------------------
__device__ __forceinline__ void mma16(float* d, const uint32_t* a,
                                      uint32_t b0, uint32_t b1) {
    asm volatile(
        "mma.sync.aligned.m16n8k16.row.col.f32.bf16.bf16.f32 "
        "{%0,%1,%2,%3}, {%4,%5,%6,%7}, {%8,%9}, {%0,%1,%2,%3};"
        : "+f"(d[0]), "+f"(d[1]), "+f"(d[2]), "+f"(d[3])
        : "r"(a[0]), "r"(a[1]), "r"(a[2]), "r"(a[3]), "r"(b0), "r"(b1));
}

// split (v0,v1) into packed bf16x2 hi + bf16x2 residual-lo ({lo16=v0, hi16=v1})
__device__ __forceinline__ void split_pack(float v0, float v1,
                                           uint32_t& hi, uint32_t& lo) {
    uint32_t h;
    asm("cvt.rn.satfinite.bf16x2.f32 %0, %1, %2;" : "=r"(h) : "f"(v1), "f"(v0));
    float h0 = __uint_as_float(h << 16);
    float h1 = __uint_as_float(h & 0xffff0000u);
    float l0 = v0 - h0, l1 = v1 - h1;
    asm("cvt.rn.satfinite.bf16x2.f32 %0, %1, %2;" : "=r"(lo) : "f"(l1), "f"(l0));
    hi = h;
}

// ---------------------------------------------------------------------------
// K1: transpose (3*C, H, W) -> (3, H, W, C)
// ---------------------------------------------------------------------------
__global__ void transpose_kernel(const float* __restrict__ tri) {
    int t = blockIdx.x * blockDim.x + threadIdx.x;
    if (t >= 3 * HH * WW) return;
    int p  = t / (HH * WW);
    int yx = t - p * (HH * WW);
    const float* src = tri + (size_t)p * CCH * HH * WW + yx;
    float v[CCH];
#pragma unroll
    for (int c = 0; c < CCH; c++) v[c] = src[(size_t)c * HH * WW];
    float4* dst = (float4*)(g_tp + (size_t)t * CCH);
#pragma unroll
    for (int k = 0; k < 8; k++)
        dst[k] = make_float4(v[4*k], v[4*k+1], v[4*k+2], v[4*k+3]);
}

// ---------------------------------------------------------------------------
// K2: cooperative sampler (unchanged from R7, proven ~50us)
// ---------------------------------------------------------------------------
__device__ __forceinline__ void sample_plane_c(const float* __restrict__ plane,
                                               float gx, float gy, int s,
                                               float4& acc) {
    float x = (gx + 1.0f) * 0.5f * (WW - 1);
    float y = (gy + 1.0f) * 0.5f * (HH - 1);
    float x0f = floorf(x), y0f = floorf(y);
    float wx = x - x0f,   wy = y - y0f;
    int x0 = (int)x0f, y0 = (int)y0f;
    int x1 = x0 + 1,   y1 = y0 + 1;

    float vxa = (x0 >= 0 && x0 < WW) ? 1.0f : 0.0f;
    float vxb = (x1 >= 0 && x1 < WW) ? 1.0f : 0.0f;
    float vya = (y0 >= 0 && y0 < HH) ? 1.0f : 0.0f;
    float vyb = (y1 >= 0 && y1 < HH) ? 1.0f : 0.0f;

    int xa = min(max(x0, 0), WW - 1);
    int xb = min(max(x1, 0), WW - 1);
    int ya = min(max(y0, 0), HH - 1);
    int yb = min(max(y1, 0), HH - 1);

    float wxs[2] = {(1.0f - wx) * vxa, wx * vxb};
    float wys[2] = {(1.0f - wy) * vya, wy * vyb};
    int   xi[2]  = {xa, xb};
    int   yi[2]  = {ya, yb};

#pragma unroll
    for (int cy = 0; cy < 2; cy++) {
#pragma unroll
        for (int cx = 0; cx < 2; cx++) {
            float w = wxs[cx] * wys[cy];
            float4 v = __ldg((const float4*)(plane +
                         (size_t)(yi[cy] * WW + xi[cx]) * CCH) + s);
            acc.x = fmaf(w, v.x, acc.x);
            acc.y = fmaf(w, v.y, acc.y);
            acc.z = fmaf(w, v.z, acc.z);
            acc.w = fmaf(w, v.w, acc.w);
        }
    }
}

__global__ void __launch_bounds__(256)
sample_kernel(const float* __restrict__ coords) {
    __shared__ float st[32 * 33];
    int tid = threadIdx.x;
    int pl  = tid >> 3;
    int s   = tid & 7;
    int pbase = blockIdx.x * 32;
    int p = pbase + pl;

    float gx = __ldg(coords + 3 * p + 0);
    float gy = __ldg(coords + 3 * p + 1);
    float gz = __ldg(coords + 3 * p + 2);

    float4 acc = make_float4(0.0f, 0.0f, 0.0f, 0.0f);
    // split order: plane0 = feat_xy, plane1 = feat_yz, plane2 = feat_xz
    sample_plane_c(g_tp,                   gx, gy, s, acc);   // feat_xy(x, y)
    sample_plane_c(g_tp + 2 * PLANE_ELEMS, gx, gz, s, acc);   // feat_xz(x, z)
    sample_plane_c(g_tp +     PLANE_ELEMS, gy, gz, s, acc);   // feat_yz(y, z)

    float* row = st + pl * 33 + 4 * s;
    row[0] = acc.x; row[1] = acc.y; row[2] = acc.z; row[3] = acc.w;
    __syncthreads();

    int b       = pbase >> 18;
    int posBase = pbase & (NPTS - 1);
    float* outb = g_sampled + (size_t)b * CCH * NPTS + posBase;
#pragma unroll
    for (int i = 0; i < 4; i++) {
        int idx = tid + 256 * i;
        int c = idx >> 5;
        int q = idx & 31;
        outb[(size_t)c * NPTS + q] = st[q * 33 + c];
    }
}

// ---------------------------------------------------------------------------
// K3: MLP 32->128->128->4 on mma.sync m16n8k16 bf16, 3xBF16 split.
// 512 thr / 16 warps = 4 warps/SMSP. Tile = 128 rows.
// Warp: stripe = wid&7 (16 rows), nhalf = wid>>3 (64 cols).
// Per-warp structure identical to R13 (proven); only warp count doubled.
// ---------------------------------------------------------------------------
#define RT 128
#define FT_STRIDE 20
#define H0_STRIDE 68
// smem uint32/float offsets
#define OFF_W1H 0          // 8192
#define OFF_W1L 8192       // 8192
#define OFF_W0H 16384      // 2048
#define OFF_W0L 18432      // 2048
#define OFF_FTH 20480      // 128*20 = 2560
#define OFF_FTL 23040      // 2560
#define OFF_H0H 25600      // 128*68 = 8704
#define OFF_H0L 34304      // 8704
#define OFF_W2T 43008      // 512
#define OFF_B0  43520      // 128
#define OFF_B1  43648      // 128
#define OFF_B2  43776      // 16
#define OFF_RED 43792      // 2*128*4 = 1024
#define SMEM_FLOATS 44816  // ~175 KB

__global__ void __launch_bounds__(512, 1)
mlp_kernel(const float* __restrict__ w0, const float* __restrict__ b0,
           const float* __restrict__ w1, const float* __restrict__ b1,
           const float* __restrict__ w2, const float* __restrict__ b2,
           float* __restrict__ out, int total) {
    extern __shared__ float smem[];
    uint32_t* s_w1h = (uint32_t*)(smem + OFF_W1H);
    uint32_t* s_w1l = (uint32_t*)(smem + OFF_W1L);
    uint32_t* s_w0h = (uint32_t*)(smem + OFF_W0H);
    uint32_t* s_w0l = (uint32_t*)(smem + OFF_W0L);
    uint32_t* s_fth = (uint32_t*)(smem + OFF_FTH);
    uint32_t* s_ftl = (uint32_t*)(smem + OFF_FTL);
    uint32_t* s_h0h = (uint32_t*)(smem + OFF_H0H);
    uint32_t* s_h0l = (uint32_t*)(smem + OFF_H0L);
    float* s_w2t = smem + OFF_W2T;
    float* s_b0  = smem + OFF_B0;
    float* s_b1  = smem + OFF_B1;
    float* s_b2  = smem + OFF_B2;
    float* s_red = smem + OFF_RED;

    int tid = threadIdx.x;

    // ---- pack w1 hi/lo in fragment lane order ----
    for (int i = tid; i < 8192; i += 512) {
        int bt = i >> 6, rem = i & 63;
        int li = rem >> 1, half = rem & 1;
        int kt = bt >> 4, nt = bt & 15;
        int g = li >> 2, tg = li & 3;
        int k0 = kt * 16 + 2 * tg + half * 8;
        int n  = nt * 8 + g;
        uint32_t hp, lp;
        split_pack(w1[n * 128 + k0], w1[n * 128 + k0 + 1], hp, lp);
        s_w1h[i] = hp;
        s_w1l[i] = lp;
    }
    // ---- pack w0 hi/lo (2 ktiles) ----
    for (int i = tid; i < 2048; i += 512) {
        int bt = i >> 6, rem = i & 63;
        int li = rem >> 1, half = rem & 1;
        int kt = bt >> 4, nt = bt & 15;
        int g = li >> 2, tg = li & 3;
        int k0 = kt * 16 + 2 * tg + half * 8;
        int n  = nt * 8 + g;
        uint32_t hp, lp;
        split_pack(w0[n * 32 + k0], w0[n * 32 + k0 + 1], hp, lp);
        s_w0h[i] = hp;
        s_w0l[i] = lp;
    }
    // w2 transposed: s_w2t[col*4 + kk] = w2[kk][col]
    if (tid < 512) s_w2t[tid] = w2[(tid & 3) * 128 + (tid >> 2)];
    if (tid < 128) { s_b0[tid] = b0[tid]; s_b1[tid] = b1[tid]; }
    if (tid < 4)   s_b2[tid] = b2[tid];
    __syncthreads();

    int lane = tid & 31;
    int wid  = tid >> 5;
    int grp  = lane >> 2;        // 0..7
    int tg   = lane & 3;         // 0..3
    int stripe = wid & 7;        // 16-row stripe (8 stripes)
    int nhalf  = wid >> 3;       // 64-col half
    int rbase  = stripe * 16;
    int rA = rbase + grp;        // A-frag row (and rA+8)

    // staging map: row = tid>>2 (0..127), kp0 = (tid&3)*4
    int srow = tid >> 2;
    int skp  = (tid & 3) * 4;

    int ntiles = total / RT;
    for (int tile = blockIdx.x; tile < ntiles; tile += gridDim.x) {
        int rowBase = tile * RT;

        // ---- stage feats: split+pack to bf16x2 hi/lo [row][kp] ----
        {
            const float4* src =
                (const float4*)(g_sampled + (size_t)(rowBase + srow) * 32 + skp * 2);
            float4 v0 = src[0], v1 = src[1];
            uint32_t hp, lp;
            split_pack(v0.x, v0.y, hp, lp);
            s_fth[srow * FT_STRIDE + skp]     = hp;
            s_ftl[srow * FT_STRIDE + skp]     = lp;
            split_pack(v0.z, v0.w, hp, lp);
            s_fth[srow * FT_STRIDE + skp + 1] = hp;
            s_ftl[srow * FT_STRIDE + skp + 1] = lp;
            split_pack(v1.x, v1.y, hp, lp);
            s_fth[srow * FT_STRIDE + skp + 2] = hp;
            s_ftl[srow * FT_STRIDE + skp + 2] = lp;
            split_pack(v1.z, v1.w, hp, lp);
            s_fth[srow * FT_STRIDE + skp + 3] = hp;
            s_ftl[srow * FT_STRIDE + skp + 3] = lp;
        }
        __syncthreads();

        // ---- layer0: acc0 = ft @ w0^T (3xBF16), K=32 = 2 ktiles ----
        float acc0[8][4];
#pragma unroll
        for (int nt = 0; nt < 8; nt++)
#pragma unroll
            for (int q = 0; q < 4; q++) acc0[nt][q] = 0.0f;

#pragma unroll
        for (int kt = 0; kt < 2; kt++) {
            uint32_t ah[4], al[4];
            ah[0] = s_fth[rA       * FT_STRIDE + kt*8 + tg];
            ah[1] = s_fth[(rA + 8) * FT_STRIDE + kt*8 + tg];
            ah[2] = s_fth[rA       * FT_STRIDE + kt*8 + tg + 4];
            ah[3] = s_fth[(rA + 8) * FT_STRIDE + kt*8 + tg + 4];
            al[0] = s_ftl[rA       * FT_STRIDE + kt*8 + tg];
            al[1] = s_ftl[(rA + 8) * FT_STRIDE + kt*8 + tg];
            al[2] = s_ftl[rA       * FT_STRIDE + kt*8 + tg + 4];
            al[3] = s_ftl[(rA + 8) * FT_STRIDE + kt*8 + tg + 4];
#pragma unroll
            for (int nt = 0; nt < 8; nt++) {
                int bt = kt * 16 + nhalf * 8 + nt;
                uint2 bh = *(const uint2*)(s_w0h + bt * 64 + lane * 2);
                uint2 bl = *(const uint2*)(s_w0l + bt * 64 + lane * 2);
                mma16(acc0[nt], ah, bh.x, bh.y);
                mma16(acc0[nt], al, bh.x, bh.y);
                mma16(acc0[nt], ah, bl.x, bl.y);
            }
        }

        // ---- epilogue0: h0 = relu(acc0 + b0) -> split bf16x2 -> s_h0 ----
#pragma unroll
        for (int nt = 0; nt < 8; nt++) {
            int col = nhalf * 64 + nt * 8 + 2 * tg;
            int cp  = col >> 1;
            float2 bv = *(const float2*)(s_b0 + col);
            uint32_t hp, lp;
            split_pack(fmaxf(acc0[nt][0] + bv.x, 0.0f),
                       fmaxf(acc0[nt][1] + bv.y, 0.0f), hp, lp);
            s_h0h[rA * H0_STRIDE + cp] = hp;
            s_h0l[rA * H0_STRIDE + cp] = lp;
            split_pack(fmaxf(acc0[nt][2] + bv.x, 0.0f),
                       fmaxf(acc0[nt][3] + bv.y, 0.0f), hp, lp);
            s_h0h[(rA + 8) * H0_STRIDE + cp] = hp;
            s_h0l[(rA + 8) * H0_STRIDE + cp] = lp;
        }
        __syncthreads();

        // ---- layer1: acc1 = h0 @ w1^T (3xBF16), K=128 = 8 ktiles ----
        float acc1[8][4];
#pragma unroll
        for (int nt = 0; nt < 8; nt++)
#pragma unroll
            for (int q = 0; q < 4; q++) acc1[nt][q] = 0.0f;

#pragma unroll
        for (int kt = 0; kt < 8; kt++) {
            uint32_t ah[4], al[4];
            ah[0] = s_h0h[rA       * H0_STRIDE + kt*8 + tg];
            ah[1] = s_h0h[(rA + 8) * H0_STRIDE + kt*8 + tg];
            ah[2] = s_h0h[rA       * H0_STRIDE + kt*8 + tg + 4];
            ah[3] = s_h0h[(rA + 8) * H0_STRIDE + kt*8 + tg + 4];
            al[0] = s_h0l[rA       * H0_STRIDE + kt*8 + tg];
            al[1] = s_h0l[(rA + 8) * H0_STRIDE + kt*8 + tg];
            al[2] = s_h0l[rA       * H0_STRIDE + kt*8 + tg + 4];
            al[3] = s_h0l[(rA + 8) * H0_STRIDE + kt*8 + tg + 4];
#pragma unroll
            for (int nt = 0; nt < 8; nt++) {
                int bt = kt * 16 + nhalf * 8 + nt;
                uint2 bh = *(const uint2*)(s_w1h + bt * 64 + lane * 2);
                uint2 bl = *(const uint2*)(s_w1l + bt * 64 + lane * 2);
                mma16(acc1[nt], ah, bh.x, bh.y);
                mma16(acc1[nt], al, bh.x, bh.y);
                mma16(acc1[nt], ah, bl.x, bl.y);
            }
        }

        // ---- layer2 partials: h1 = relu(acc1 + b1); p += h1 * w2t ----
        float p0[4] = {0, 0, 0, 0};   // row rA
        float p1[4] = {0, 0, 0, 0};   // row rA+8
#pragma unroll
        for (int nt = 0; nt < 8; nt++) {
            int col = nhalf * 64 + nt * 8 + 2 * tg;
            float2 bv = *(const float2*)(s_b1 + col);
            float h00 = fmaxf(acc1[nt][0] + bv.x, 0.0f);
            float h01 = fmaxf(acc1[nt][1] + bv.y, 0.0f);
            float h10 = fmaxf(acc1[nt][2] + bv.x, 0.0f);
            float h11 = fmaxf(acc1[nt][3] + bv.y, 0.0f);
            float4 wv0 = *(const float4*)(s_w2t + col * 4);
            float4 wv1 = *(const float4*)(s_w2t + (col + 1) * 4);
            p0[0] = fmaf(h00, wv0.x, fmaf(h01, wv1.x, p0[0]));
            p0[1] = fmaf(h00, wv0.y, fmaf(h01, wv1.y, p0[1]));
            p0[2] = fmaf(h00, wv0.z, fmaf(h01, wv1.z, p0[2]));
            p0[3] = fmaf(h00, wv0.w, fmaf(h01, wv1.w, p0[3]));
            p1[0] = fmaf(h10, wv0.x, fmaf(h11, wv1.x, p1[0]));
            p1[1] = fmaf(h10, wv0.y, fmaf(h11, wv1.y, p1[1]));
            p1[2] = fmaf(h10, wv0.z, fmaf(h11, wv1.z, p1[2]));
            p1[3] = fmaf(h10, wv0.w, fmaf(h11, wv1.w, p1[3]));
        }
        // reduce across the quad (tg dimension)
#pragma unroll
        for (int off = 1; off <= 2; off <<= 1) {
#pragma unroll
            for (int q = 0; q < 4; q++) {
                p0[q] += __shfl_xor_sync(0xffffffffu, p0[q], off);
                p1[q] += __shfl_xor_sync(0xffffffffu, p1[q], off);
            }
        }
        if (tg == 0) {
            *(float4*)(s_red + (size_t)(nhalf * 128 + rA) * 4) =
                make_float4(p0[0], p0[1], p0[2], p0[3]);
            *(float4*)(s_red + (size_t)(nhalf * 128 + rA + 8) * 4) =
                make_float4(p1[0], p1[1], p1[2], p1[3]);
        }
        __syncthreads();

        // ---- final: sum col-halves, bias, relu, permute, store ----
        if (tid < RT) {
            float4 v0 = *(const float4*)(s_red + (size_t)tid * 4);
            float4 v1 = *(const float4*)(s_red + (size_t)(128 + tid) * 4);
            float o0 = fmaxf(s_b2[0] + v0.x + v1.x, 0.0f);
            float o1 = fmaxf(s_b2[1] + v0.y + v1.y, 0.0f);
            float o2 = fmaxf(s_b2[2] + v0.z + v1.z, 0.0f);
            float o3 = fmaxf(s_b2[3] + v0.w + v1.w, 0.0f);
            // raw = concat(net[...,1:4], net[...,0:1])
            ((float4*)out)[rowBase + tid] = make_float4(o1, o2, o3, o0);
        }
        __syncthreads();
    }
}

// ---------------------------------------------------------------------------
extern "C" void kernel_launch(void* const* d_in, const int* in_sizes, int n_in,
                              void* d_out, int out_size) {
    const float* coords = (const float*)d_in[0];
    const float* tri    = (const float*)d_in[1];
    const float* w0     = (const float*)d_in[2];
    const float* b0     = (const float*)d_in[3];
    const float* w1     = (const float*)d_in[4];
    const float* b1     = (const float*)d_in[5];
    const float* w2     = (const float*)d_in[6];
    const float* b2     = (const float*)d_in[7];
    float* out = (float*)d_out;

    int total = in_sizes[0] / 3;   // B * N points = MLP rows

    transpose_kernel<<<(3 * HH * WW + 127) / 128, 128>>>(tri);
    sample_kernel<<<total / 32, 256>>>(coords);

    int mlp_smem = SMEM_FLOATS * 4;   // ~175 KB dynamic shared
    cudaFuncSetAttribute(mlp_kernel,
                         cudaFuncAttributeMaxDynamicSharedMemorySize, mlp_smem);
    mlp_kernel<<<148, 512, mlp_smem>>>(w0, b0, w1, b1, w2, b2, out, total);
}

// round 15
// speedup vs baseline: 2.4200x; 1.1682x over previous
#include <cuda_runtime.h>
#include <cuda_fp16.h>
#include <cstdint>

#define CCH 32
#define HH 128
#define WW 128
#define NPTS 262144
#define PLANE_ELEMS (HH * WW * CCH)

// Transposed triplanes: (plane, y, x, c) -- 6.3 MB, L2-resident
__device__ float g_tp[3 * PLANE_ELEMS];
// Sampled features in (b, c, pos) layout; MLP row r reads flat [r*32 .. r*32+31]
__device__ float g_sampled[4 * CCH * NPTS];   // 134 MB

// ---------------------------------------------------------------------------
// fp16 helpers + mma.sync m16n8k16 (fallback HMMA on sm_103a)
// ---------------------------------------------------------------------------
__device__ __forceinline__ void mma16(float* d, const uint32_t* a,
                                      uint32_t b0, uint32_t b1) {
    asm volatile(
        "mma.sync.aligned.m16n8k16.row.col.f32.f16.f16.f32 "
        "{%0,%1,%2,%3}, {%4,%5,%6,%7}, {%8,%9}, {%0,%1,%2,%3};"
        : "+f"(d[0]), "+f"(d[1]), "+f"(d[2]), "+f"(d[3])
        : "r"(a[0]), "r"(a[1]), "r"(a[2]), "r"(a[3]), "r"(b0), "r"(b1));
}

// pack (v0,v1) to fp16x2 {lo16=v0, hi16=v1}
__device__ __forceinline__ uint32_t pack_f16(float v0, float v1) {
    __half2 h = __floats2half2_rn(v0, v1);
    return *(uint32_t*)&h;
}
// split (v0,v1) into fp16x2 hi + fp16x2 residual-lo
__device__ __forceinline__ void split_pack_f16(float v0, float v1,
                                               uint32_t& hi, uint32_t& lo) {
    __half2 h = __floats2half2_rn(v0, v1);
    float2 hf = __half22float2(h);
    __half2 l = __floats2half2_rn(v0 - hf.x, v1 - hf.y);
    hi = *(uint32_t*)&h;
    lo = *(uint32_t*)&l;
}

// ---------------------------------------------------------------------------
// K1: transpose (3*C, H, W) -> (3, H, W, C)
// ---------------------------------------------------------------------------
__global__ void transpose_kernel(const float* __restrict__ tri) {
    int t = blockIdx.x * blockDim.x + threadIdx.x;
    if (t >= 3 * HH * WW) return;
    int p  = t / (HH * WW);
    int yx = t - p * (HH * WW);
    const float* src = tri + (size_t)p * CCH * HH * WW + yx;
    float v[CCH];
#pragma unroll
    for (int c = 0; c < CCH; c++) v[c] = src[(size_t)c * HH * WW];
    float4* dst = (float4*)(g_tp + (size_t)t * CCH);
#pragma unroll
    for (int k = 0; k < 8; k++)
        dst[k] = make_float4(v[4*k], v[4*k+1], v[4*k+2], v[4*k+3]);
}

// ---------------------------------------------------------------------------
// K2: cooperative sampler (unchanged from R7, proven ~50us)
// ---------------------------------------------------------------------------
__device__ __forceinline__ void sample_plane_c(const float* __restrict__ plane,
                                               float gx, float gy, int s,
                                               float4& acc) {
    float x = (gx + 1.0f) * 0.5f * (WW - 1);
    float y = (gy + 1.0f) * 0.5f * (HH - 1);
    float x0f = floorf(x), y0f = floorf(y);
    float wx = x - x0f,   wy = y - y0f;
    int x0 = (int)x0f, y0 = (int)y0f;
    int x1 = x0 + 1,   y1 = y0 + 1;

    float vxa = (x0 >= 0 && x0 < WW) ? 1.0f : 0.0f;
    float vxb = (x1 >= 0 && x1 < WW) ? 1.0f : 0.0f;
    float vya = (y0 >= 0 && y0 < HH) ? 1.0f : 0.0f;
    float vyb = (y1 >= 0 && y1 < HH) ? 1.0f : 0.0f;

    int xa = min(max(x0, 0), WW - 1);
    int xb = min(max(x1, 0), WW - 1);
    int ya = min(max(y0, 0), HH - 1);
    int yb = min(max(y1, 0), HH - 1);

    float wxs[2] = {(1.0f - wx) * vxa, wx * vxb};
    float wys[2] = {(1.0f - wy) * vya, wy * vyb};
    int   xi[2]  = {xa, xb};
    int   yi[2]  = {ya, yb};

#pragma unroll
    for (int cy = 0; cy < 2; cy++) {
#pragma unroll
        for (int cx = 0; cx < 2; cx++) {
            float w = wxs[cx] * wys[cy];
            float4 v = __ldg((const float4*)(plane +
                         (size_t)(yi[cy] * WW + xi[cx]) * CCH) + s);
            acc.x = fmaf(w, v.x, acc.x);
            acc.y = fmaf(w, v.y, acc.y);
            acc.z = fmaf(w, v.z, acc.z);
            acc.w = fmaf(w, v.w, acc.w);
        }
    }
}

__global__ void __launch_bounds__(256)
sample_kernel(const float* __restrict__ coords) {
    __shared__ float st[32 * 33];
    int tid = threadIdx.x;
    int pl  = tid >> 3;
    int s   = tid & 7;
    int pbase = blockIdx.x * 32;
    int p = pbase + pl;

    float gx = __ldg(coords + 3 * p + 0);
    float gy = __ldg(coords + 3 * p + 1);
    float gz = __ldg(coords + 3 * p + 2);

    float4 acc = make_float4(0.0f, 0.0f, 0.0f, 0.0f);
    // split order: plane0 = feat_xy, plane1 = feat_yz, plane2 = feat_xz
    sample_plane_c(g_tp,                   gx, gy, s, acc);   // feat_xy(x, y)
    sample_plane_c(g_tp + 2 * PLANE_ELEMS, gx, gz, s, acc);   // feat_xz(x, z)
    sample_plane_c(g_tp +     PLANE_ELEMS, gy, gz, s, acc);   // feat_yz(y, z)

    float* row = st + pl * 33 + 4 * s;
    row[0] = acc.x; row[1] = acc.y; row[2] = acc.z; row[3] = acc.w;
    __syncthreads();

    int b       = pbase >> 18;
    int posBase = pbase & (NPTS - 1);
    float* outb = g_sampled + (size_t)b * CCH * NPTS + posBase;
#pragma unroll
    for (int i = 0; i < 4; i++) {
        int idx = tid + 256 * i;
        int c = idx >> 5;
        int q = idx & 31;
        outb[(size_t)c * NPTS + q] = st[q * 33 + c];
    }
}

// ---------------------------------------------------------------------------
// K3: MLP 32->128->128->4 on mma.sync m16n8k16 fp16 with 2-term split:
//   activations single fp16, weights fp16 hi + residual lo.
//   x*w = xh*wh + xh*wl (= xh*w); error = activation rounding ~2^-12.
// 512 thr / 16 warps = 4 warps/SMSP. Tile = 128 rows.
// ---------------------------------------------------------------------------
#define RT 128
#define FT_STRIDE 20
#define H0_STRIDE 68
// smem uint32/float offsets
#define OFF_W1H 0          // 8192
#define OFF_W1L 8192       // 8192
#define OFF_W0H 16384      // 2048
#define OFF_W0L 18432      // 2048
#define OFF_FTH 20480      // 128*20 = 2560
#define OFF_H0H 23040      // 128*68 = 8704
#define OFF_W2T 31744      // 512
#define OFF_B0  32256      // 128
#define OFF_B1  32384      // 128
#define OFF_B2  32512      // 16
#define OFF_RED 32528      // 2*128*4 = 1024
#define SMEM_FLOATS 33552  // ~134 KB

__global__ void __launch_bounds__(512, 1)
mlp_kernel(const float* __restrict__ w0, const float* __restrict__ b0,
           const float* __restrict__ w1, const float* __restrict__ b1,
           const float* __restrict__ w2, const float* __restrict__ b2,
           float* __restrict__ out, int total) {
    extern __shared__ float smem[];
    uint32_t* s_w1h = (uint32_t*)(smem + OFF_W1H);
    uint32_t* s_w1l = (uint32_t*)(smem + OFF_W1L);
    uint32_t* s_w0h = (uint32_t*)(smem + OFF_W0H);
    uint32_t* s_w0l = (uint32_t*)(smem + OFF_W0L);
    uint32_t* s_fth = (uint32_t*)(smem + OFF_FTH);
    uint32_t* s_h0h = (uint32_t*)(smem + OFF_H0H);
    float* s_w2t = smem + OFF_W2T;
    float* s_b0  = smem + OFF_B0;
    float* s_b1  = smem + OFF_B1;
    float* s_b2  = smem + OFF_B2;
    float* s_red = smem + OFF_RED;

    int tid = threadIdx.x;

    // ---- pack w1 fp16 hi/lo in fragment lane order ----
    for (int i = tid; i < 8192; i += 512) {
        int bt = i >> 6, rem = i & 63;
        int li = rem >> 1, half = rem & 1;
        int kt = bt >> 4, nt = bt & 15;
        int g = li >> 2, tg = li & 3;
        int k0 = kt * 16 + 2 * tg + half * 8;
        int n  = nt * 8 + g;
        uint32_t hp, lp;
        split_pack_f16(w1[n * 128 + k0], w1[n * 128 + k0 + 1], hp, lp);
        s_w1h[i] = hp;
        s_w1l[i] = lp;
    }
    // ---- pack w0 fp16 hi/lo (2 ktiles) ----
    for (int i = tid; i < 2048; i += 512) {
        int bt = i >> 6, rem = i & 63;
        int li = rem >> 1, half = rem & 1;
        int kt = bt >> 4, nt = bt & 15;
        int g = li >> 2, tg = li & 3;
        int k0 = kt * 16 + 2 * tg + half * 8;
        int n  = nt * 8 + g;
        uint32_t hp, lp;
        split_pack_f16(w0[n * 32 + k0], w0[n * 32 + k0 + 1], hp, lp);
        s_w0h[i] = hp;
        s_w0l[i] = lp;
    }
    // w2 transposed: s_w2t[col*4 + kk] = w2[kk][col]
    if (tid < 512) s_w2t[tid] = w2[(tid & 3) * 128 + (tid >> 2)];
    if (tid < 128) { s_b0[tid] = b0[tid]; s_b1[tid] = b1[tid]; }
    if (tid < 4)   s_b2[tid] = b2[tid];
    __syncthreads();

    int lane = tid & 31;
    int wid  = tid >> 5;
    int grp  = lane >> 2;        // 0..7
    int tg   = lane & 3;         // 0..3
    int stripe = wid & 7;        // 16-row stripe
    int nhalf  = wid >> 3;       // 64-col half
    int rbase  = stripe * 16;
    int rA = rbase + grp;        // A-frag row (and rA+8)

    // staging map: row = tid>>2 (0..127), kp0 = (tid&3)*4
    int srow = tid >> 2;
    int skp  = (tid & 3) * 4;

    int ntiles = total / RT;
    for (int tile = blockIdx.x; tile < ntiles; tile += gridDim.x) {
        int rowBase = tile * RT;

        // ---- stage feats as single fp16x2 [row][kp] ----
        {
            const float4* src =
                (const float4*)(g_sampled + (size_t)(rowBase + srow) * 32 + skp * 2);
            float4 v0 = src[0], v1 = src[1];
            s_fth[srow * FT_STRIDE + skp]     = pack_f16(v0.x, v0.y);
            s_fth[srow * FT_STRIDE + skp + 1] = pack_f16(v0.z, v0.w);
            s_fth[srow * FT_STRIDE + skp + 2] = pack_f16(v1.x, v1.y);
            s_fth[srow * FT_STRIDE + skp + 3] = pack_f16(v1.z, v1.w);
        }
        __syncthreads();

        // ---- layer0: acc0 = ft @ w0^T (2-term), K=32 = 2 ktiles ----
        float acc0[8][4];
#pragma unroll
        for (int nt = 0; nt < 8; nt++)
#pragma unroll
            for (int q = 0; q < 4; q++) acc0[nt][q] = 0.0f;

#pragma unroll
        for (int kt = 0; kt < 2; kt++) {
            uint32_t ah[4];
            ah[0] = s_fth[rA       * FT_STRIDE + kt*8 + tg];
            ah[1] = s_fth[(rA + 8) * FT_STRIDE + kt*8 + tg];
            ah[2] = s_fth[rA       * FT_STRIDE + kt*8 + tg + 4];
            ah[3] = s_fth[(rA + 8) * FT_STRIDE + kt*8 + tg + 4];
#pragma unroll
            for (int nt = 0; nt < 8; nt++) {
                int bt = kt * 16 + nhalf * 8 + nt;
                uint2 bh = *(const uint2*)(s_w0h + bt * 64 + lane * 2);
                uint2 bl = *(const uint2*)(s_w0l + bt * 64 + lane * 2);
                mma16(acc0[nt], ah, bh.x, bh.y);
                mma16(acc0[nt], ah, bl.x, bl.y);
            }
        }

        // ---- epilogue0: h0 = relu(acc0 + b0) -> fp16x2 -> s_h0 ----
#pragma unroll
        for (int nt = 0; nt < 8; nt++) {
            int col = nhalf * 64 + nt * 8 + 2 * tg;
            int cp  = col >> 1;
            float2 bv = *(const float2*)(s_b0 + col);
            s_h0h[rA * H0_STRIDE + cp] =
                pack_f16(fmaxf(acc0[nt][0] + bv.x, 0.0f),
                         fmaxf(acc0[nt][1] + bv.y, 0.0f));
            s_h0h[(rA + 8) * H0_STRIDE + cp] =
                pack_f16(fmaxf(acc0[nt][2] + bv.x, 0.0f),
                         fmaxf(acc0[nt][3] + bv.y, 0.0f));
        }
        __syncthreads();

        // ---- layer1: acc1 = h0 @ w1^T (2-term), K=128 = 8 ktiles ----
        float acc1[8][4];
#pragma unroll
        for (int nt = 0; nt < 8; nt++)
#pragma unroll
            for (int q = 0; q < 4; q++) acc1[nt][q] = 0.0f;

#pragma unroll
        for (int kt = 0; kt < 8; kt++) {
            uint32_t ah[4];
            ah[0] = s_h0h[rA       * H0_STRIDE + kt*8 + tg];
            ah[1] = s_h0h[(rA + 8) * H0_STRIDE + kt*8 + tg];
            ah[2] = s_h0h[rA       * H0_STRIDE + kt*8 + tg + 4];
            ah[3] = s_h0h[(rA + 8) * H0_STRIDE + kt*8 + tg + 4];
#pragma unroll
            for (int nt = 0; nt < 8; nt++) {
                int bt = kt * 16 + nhalf * 8 + nt;
                uint2 bh = *(const uint2*)(s_w1h + bt * 64 + lane * 2);
                uint2 bl = *(const uint2*)(s_w1l + bt * 64 + lane * 2);
                mma16(acc1[nt], ah, bh.x, bh.y);
                mma16(acc1[nt], ah, bl.x, bl.y);
            }
        }

        // ---- layer2 partials: h1 = relu(acc1 + b1); p += h1 * w2t ----
        float p0[4] = {0, 0, 0, 0};   // row rA
        float p1[4] = {0, 0, 0, 0};   // row rA+8
#pragma unroll
        for (int nt = 0; nt < 8; nt++) {
            int col = nhalf * 64 + nt * 8 + 2 * tg;
            float2 bv = *(const float2*)(s_b1 + col);
            float h00 = fmaxf(acc1[nt][0] + bv.x, 0.0f);
            float h01 = fmaxf(acc1[nt][1] + bv.y, 0.0f);
            float h10 = fmaxf(acc1[nt][2] + bv.x, 0.0f);
            float h11 = fmaxf(acc1[nt][3] + bv.y, 0.0f);
            float4 wv0 = *(const float4*)(s_w2t + col * 4);
            float4 wv1 = *(const float4*)(s_w2t + (col + 1) * 4);
            p0[0] = fmaf(h00, wv0.x, fmaf(h01, wv1.x, p0[0]));
            p0[1] = fmaf(h00, wv0.y, fmaf(h01, wv1.y, p0[1]));
            p0[2] = fmaf(h00, wv0.z, fmaf(h01, wv1.z, p0[2]));
            p0[3] = fmaf(h00, wv0.w, fmaf(h01, wv1.w, p0[3]));
            p1[0] = fmaf(h10, wv0.x, fmaf(h11, wv1.x, p1[0]));
            p1[1] = fmaf(h10, wv0.y, fmaf(h11, wv1.y, p1[1]));
            p1[2] = fmaf(h10, wv0.z, fmaf(h11, wv1.z, p1[2]));
            p1[3] = fmaf(h10, wv0.w, fmaf(h11, wv1.w, p1[3]));
        }
        // reduce across the quad (tg dimension)
#pragma unroll
        for (int off = 1; off <= 2; off <<= 1) {
#pragma unroll
            for (int q = 0; q < 4; q++) {
                p0[q] += __shfl_xor_sync(0xffffffffu, p0[q], off);
                p1[q] += __shfl_xor_sync(0xffffffffu, p1[q], off);
            }
        }
        if (tg == 0) {
            *(float4*)(s_red + (size_t)(nhalf * 128 + rA) * 4) =
                make_float4(p0[0], p0[1], p0[2], p0[3]);
            *(float4*)(s_red + (size_t)(nhalf * 128 + rA + 8) * 4) =
                make_float4(p1[0], p1[1], p1[2], p1[3]);
        }
        __syncthreads();

        // ---- final: sum col-halves, bias, relu, permute, store ----
        if (tid < RT) {
            float4 v0 = *(const float4*)(s_red + (size_t)tid * 4);
            float4 v1 = *(const float4*)(s_red + (size_t)(128 + tid) * 4);
            float o0 = fmaxf(s_b2[0] + v0.x + v1.x, 0.0f);
            float o1 = fmaxf(s_b2[1] + v0.y + v1.y, 0.0f);
            float o2 = fmaxf(s_b2[2] + v0.z + v1.z, 0.0f);
            float o3 = fmaxf(s_b2[3] + v0.w + v1.w, 0.0f);
            // raw = concat(net[...,1:4], net[...,0:1])
            ((float4*)out)[rowBase + tid] = make_float4(o1, o2, o3, o0);
        }
        __syncthreads();
    }
}

// ---------------------------------------------------------------------------
extern "C" void kernel_launch(void* const* d_in, const int* in_sizes, int n_in,
                              void* d_out, int out_size) {
    const float* coords = (const float*)d_in[0];
    const float* tri    = (const float*)d_in[1];
    const float* w0     = (const float*)d_in[2];
    const float* b0     = (const float*)d_in[3];
    const float* w1     = (const float*)d_in[4];
    const float* b1     = (const float*)d_in[5];
    const float* w2     = (const float*)d_in[6];
    const float* b2     = (const float*)d_in[7];
    float* out = (float*)d_out;

    int total = in_sizes[0] / 3;   // B * N points = MLP rows

    transpose_kernel<<<(3 * HH * WW + 127) / 128, 128>>>(tri);
    sample_kernel<<<total / 32, 256>>>(coords);

    int mlp_smem = SMEM_FLOATS * 4;   // ~134 KB dynamic shared
    cudaFuncSetAttribute(mlp_kernel,
                         cudaFuncAttributeMaxDynamicSharedMemorySize, mlp_smem);
    mlp_kernel<<<148, 512, mlp_smem>>>(w0, b0, w1, b1, w2, b2, out, total);
}

// round 16
// speedup vs baseline: 3.0817x; 1.2734x over previous
#include <cuda_runtime.h>
#include <cuda_fp16.h>
#include <cstdint>

#define CCH 32
#define HH 128
#define WW 128
#define NPTS 262144
#define PLANE_ELEMS (HH * WW * CCH)

// Transposed triplanes: (plane, y, x, c) -- 6.3 MB, L2-resident
__device__ float g_tp[3 * PLANE_ELEMS];
// Sampled features in (b, c, pos) layout; MLP row r reads flat [r*32 .. r*32+31]
__device__ float g_sampled[4 * CCH * NPTS];   // 134 MB

// ---------------------------------------------------------------------------
// fp16 helpers + mma.sync m16n8k16
// ---------------------------------------------------------------------------
__device__ __forceinline__ void mma16(float* d, const uint32_t* a,
                                      uint32_t b0, uint32_t b1) {
    asm volatile(
        "mma.sync.aligned.m16n8k16.row.col.f32.f16.f16.f32 "
        "{%0,%1,%2,%3}, {%4,%5,%6,%7}, {%8,%9}, {%0,%1,%2,%3};"
        : "+f"(d[0]), "+f"(d[1]), "+f"(d[2]), "+f"(d[3])
        : "r"(a[0]), "r"(a[1]), "r"(a[2]), "r"(a[3]), "r"(b0), "r"(b1));
}
__device__ __forceinline__ uint32_t pack_f16(float v0, float v1) {
    __half2 h = __floats2half2_rn(v0, v1);
    return *(uint32_t*)&h;
}
__device__ __forceinline__ void split_pack_f16(float v0, float v1,
                                               uint32_t& hi, uint32_t& lo) {
    __half2 h = __floats2half2_rn(v0, v1);
    float2 hf = __half22float2(h);
    __half2 l = __floats2half2_rn(v0 - hf.x, v1 - hf.y);
    hi = *(uint32_t*)&h;
    lo = *(uint32_t*)&l;
}

// ---------------------------------------------------------------------------
// K1: transpose (3*C, H, W) -> (3, H, W, C)
// ---------------------------------------------------------------------------
__global__ void transpose_kernel(const float* __restrict__ tri) {
    int t = blockIdx.x * blockDim.x + threadIdx.x;
    if (t >= 3 * HH * WW) return;
    int p  = t / (HH * WW);
    int yx = t - p * (HH * WW);
    const float* src = tri + (size_t)p * CCH * HH * WW + yx;
    float v[CCH];
#pragma unroll
    for (int c = 0; c < CCH; c++) v[c] = src[(size_t)c * HH * WW];
    float4* dst = (float4*)(g_tp + (size_t)t * CCH);
#pragma unroll
    for (int k = 0; k < 8; k++)
        dst[k] = make_float4(v[4*k], v[4*k+1], v[4*k+2], v[4*k+3]);
}

// ---------------------------------------------------------------------------
// K2: cooperative sampler (unchanged, proven ~50us)
// ---------------------------------------------------------------------------
__device__ __forceinline__ void sample_plane_c(const float* __restrict__ plane,
                                               float gx, float gy, int s,
                                               float4& acc) {
    float x = (gx + 1.0f) * 0.5f * (WW - 1);
    float y = (gy + 1.0f) * 0.5f * (HH - 1);
    float x0f = floorf(x), y0f = floorf(y);
    float wx = x - x0f,   wy = y - y0f;
    int x0 = (int)x0f, y0 = (int)y0f;
    int x1 = x0 + 1,   y1 = y0 + 1;

    float vxa = (x0 >= 0 && x0 < WW) ? 1.0f : 0.0f;
    float vxb = (x1 >= 0 && x1 < WW) ? 1.0f : 0.0f;
    float vya = (y0 >= 0 && y0 < HH) ? 1.0f : 0.0f;
    float vyb = (y1 >= 0 && y1 < HH) ? 1.0f : 0.0f;

    int xa = min(max(x0, 0), WW - 1);
    int xb = min(max(x1, 0), WW - 1);
    int ya = min(max(y0, 0), HH - 1);
    int yb = min(max(y1, 0), HH - 1);

    float wxs[2] = {(1.0f - wx) * vxa, wx * vxb};
    float wys[2] = {(1.0f - wy) * vya, wy * vyb};
    int   xi[2]  = {xa, xb};
    int   yi[2]  = {ya, yb};

#pragma unroll
    for (int cy = 0; cy < 2; cy++) {
#pragma unroll
        for (int cx = 0; cx < 2; cx++) {
            float w = wxs[cx] * wys[cy];
            float4 v = __ldg((const float4*)(plane +
                         (size_t)(yi[cy] * WW + xi[cx]) * CCH) + s);
            acc.x = fmaf(w, v.x, acc.x);
            acc.y = fmaf(w, v.y, acc.y);
            acc.z = fmaf(w, v.z, acc.z);
            acc.w = fmaf(w, v.w, acc.w);
        }
    }
}

__global__ void __launch_bounds__(256)
sample_kernel(const float* __restrict__ coords) {
    __shared__ float st[32 * 33];
    int tid = threadIdx.x;
    int pl  = tid >> 3;
    int s   = tid & 7;
    int pbase = blockIdx.x * 32;
    int p = pbase + pl;

    float gx = __ldg(coords + 3 * p + 0);
    float gy = __ldg(coords + 3 * p + 1);
    float gz = __ldg(coords + 3 * p + 2);

    float4 acc = make_float4(0.0f, 0.0f, 0.0f, 0.0f);
    // split order: plane0 = feat_xy, plane1 = feat_yz, plane2 = feat_xz
    sample_plane_c(g_tp,                   gx, gy, s, acc);   // feat_xy(x, y)
    sample_plane_c(g_tp + 2 * PLANE_ELEMS, gx, gz, s, acc);   // feat_xz(x, z)
    sample_plane_c(g_tp +     PLANE_ELEMS, gy, gz, s, acc);   // feat_yz(y, z)

    float* row = st + pl * 33 + 4 * s;
    row[0] = acc.x; row[1] = acc.y; row[2] = acc.z; row[3] = acc.w;
    __syncthreads();

    int b       = pbase >> 18;
    int posBase = pbase & (NPTS - 1);
    float* outb = g_sampled + (size_t)b * CCH * NPTS + posBase;
#pragma unroll
    for (int i = 0; i < 4; i++) {
        int idx = tid + 256 * i;
        int c = idx >> 5;
        int q = idx & 31;
        outb[(size_t)c * NPTS + q] = st[q * 33 + c];
    }
}

// ---------------------------------------------------------------------------
// K3: MLP 32->128->128->4, fully warp-local, barrier-free tile loop.
// Each warp owns 16 rows x ALL 128 cols. Layer0 accumulators ARE layer1
// A-fragments after bias+relu+pack (register permutation, no smem).
// Weights in smem as fused hi/lo uint4 fragments (one LDS.128 each).
// 2-term fp16 split: activations fp16, weights fp16 hi + residual lo.
// ---------------------------------------------------------------------------
// smem uint32 offsets
#define OFF_W1F 0          // 128 bt * 128 = 16384 u32 (uint4 {bh0,bh1,bl0,bl1})
#define OFF_W0F 16384      // 32 bt * 128 = 4096
#define OFF_W2T 20480      // 512 floats
#define OFF_B0  20992      // 128
#define OFF_B1  21120      // 128
#define OFF_B2  21248      // 4 (pad 16)
#define SMEM_U32 21264     // ~85 KB

__global__ void __launch_bounds__(512)
mlp_kernel(const float* __restrict__ w0, const float* __restrict__ b0,
           const float* __restrict__ w1, const float* __restrict__ b1,
           const float* __restrict__ w2, const float* __restrict__ b2,
           float* __restrict__ out, int total) {
    extern __shared__ uint32_t smem[];
    uint4* s_w1f = (uint4*)(smem + OFF_W1F);   // [bt*32 + lane]
    uint4* s_w0f = (uint4*)(smem + OFF_W0F);
    float* s_w2t = (float*)(smem + OFF_W2T);
    float* s_b0  = (float*)(smem + OFF_B0);
    float* s_b1  = (float*)(smem + OFF_B1);
    float* s_b2  = (float*)(smem + OFF_B2);

    int tid = threadIdx.x;

    // ---- pack w1 fragments: bt = kt*16+nt (kt 0..7), entry per lane ----
    for (int i = tid; i < 4096; i += 512) {
        int bt = i >> 5, li = i & 31;
        int kt = bt >> 4, nt = bt & 15;
        int g = li >> 2, tg = li & 3;
        int n  = nt * 8 + g;
        int k0 = kt * 16 + 2 * tg;
        uint32_t h0p, l0p, h1p, l1p;
        split_pack_f16(w1[n * 128 + k0],     w1[n * 128 + k0 + 1], h0p, l0p);
        split_pack_f16(w1[n * 128 + k0 + 8], w1[n * 128 + k0 + 9], h1p, l1p);
        s_w1f[i] = make_uint4(h0p, h1p, l0p, l1p);
    }
    // ---- pack w0 fragments: bt = kt*16+nt (kt 0..1) ----
    for (int i = tid; i < 1024; i += 512) {
        int bt = i >> 5, li = i & 31;
        int kt = bt >> 4, nt = bt & 15;
        int g = li >> 2, tg = li & 3;
        int n  = nt * 8 + g;
        int k0 = kt * 16 + 2 * tg;
        uint32_t h0p, l0p, h1p, l1p;
        split_pack_f16(w0[n * 32 + k0],     w0[n * 32 + k0 + 1], h0p, l0p);
        split_pack_f16(w0[n * 32 + k0 + 8], w0[n * 32 + k0 + 9], h1p, l1p);
        s_w0f[i] = make_uint4(h0p, h1p, l0p, l1p);
    }
    // w2 transposed: s_w2t[col*4 + kk] = w2[kk][col]
    if (tid < 512) s_w2t[tid] = w2[(tid & 3) * 128 + (tid >> 2)];
    if (tid < 128) { s_b0[tid] = b0[tid]; s_b1[tid] = b1[tid]; }
    if (tid < 4)   s_b2[tid] = b2[tid];
    __syncthreads();   // weights ready; no further syncs

    int lane = tid & 31;
    int wid  = tid >> 5;
    int g    = lane >> 2;      // 0..7
    int tg   = lane & 3;       // 0..3

    int nwt    = total >> 4;                   // warp-tiles of 16 rows
    int wt0    = blockIdx.x * 16 + wid;        // global warp index
    int stride = gridDim.x * 16;

    for (int wt = wt0; wt < nwt; wt += stride) {
        int r0 = (wt << 4) + g;     // rows r0, r0+8
        const float* fr0 = g_sampled + (size_t)r0 * 32;
        const float* fr1 = fr0 + 8 * 32;

        // ---- load + pack layer0 A-fragments from gmem ----
        uint32_t a0[2][4];
#pragma unroll
        for (int kt = 0; kt < 2; kt++) {
            float2 v;
            v = *(const float2*)(fr0 + kt * 16 + 2 * tg);
            a0[kt][0] = pack_f16(v.x, v.y);
            v = *(const float2*)(fr1 + kt * 16 + 2 * tg);
            a0[kt][1] = pack_f16(v.x, v.y);
            v = *(const float2*)(fr0 + kt * 16 + 2 * tg + 8);
            a0[kt][2] = pack_f16(v.x, v.y);
            v = *(const float2*)(fr1 + kt * 16 + 2 * tg + 8);
            a0[kt][3] = pack_f16(v.x, v.y);
        }

        // ---- layer0: acc0[nt] over all 16 n-tiles ----
        float acc0[16][4];
#pragma unroll
        for (int nt = 0; nt < 16; nt++)
#pragma unroll
            for (int q = 0; q < 4; q++) acc0[nt][q] = 0.0f;

#pragma unroll
        for (int kt = 0; kt < 2; kt++)
#pragma unroll
            for (int nt = 0; nt < 16; nt++) {
                uint4 wf = s_w0f[(kt * 16 + nt) * 32 + lane];
                mma16(acc0[nt], a0[kt], wf.x, wf.y);
                mma16(acc0[nt], a0[kt], wf.z, wf.w);
            }

        // ---- epilogue0: bias+relu+pack acc0 -> layer1 A-frags (registers) ----
        uint32_t a1[8][4];
#pragma unroll
        for (int kt = 0; kt < 8; kt++) {
            float2 bA = *(const float2*)(s_b0 + 16 * kt + 2 * tg);
            float2 bB = *(const float2*)(s_b0 + 16 * kt + 2 * tg + 8);
            a1[kt][0] = pack_f16(fmaxf(acc0[2*kt][0] + bA.x, 0.0f),
                                 fmaxf(acc0[2*kt][1] + bA.y, 0.0f));
            a1[kt][1] = pack_f16(fmaxf(acc0[2*kt][2] + bA.x, 0.0f),
                                 fmaxf(acc0[2*kt][3] + bA.y, 0.0f));
            a1[kt][2] = pack_f16(fmaxf(acc0[2*kt+1][0] + bB.x, 0.0f),
                                 fmaxf(acc0[2*kt+1][1] + bB.y, 0.0f));
            a1[kt][3] = pack_f16(fmaxf(acc0[2*kt+1][2] + bB.x, 0.0f),
                                 fmaxf(acc0[2*kt+1][3] + bB.y, 0.0f));
        }

        // ---- layer1 + layer2 in two n-halves (caps registers) ----
        float p0[4] = {0, 0, 0, 0};
        float p1[4] = {0, 0, 0, 0};
#pragma unroll
        for (int half = 0; half < 2; half++) {
            float acc1[8][4];
#pragma unroll
            for (int nt = 0; nt < 8; nt++)
#pragma unroll
                for (int q = 0; q < 4; q++) acc1[nt][q] = 0.0f;

#pragma unroll
            for (int kt = 0; kt < 8; kt++)
#pragma unroll
                for (int nt = 0; nt < 8; nt++) {
                    uint4 wf = s_w1f[(kt * 16 + half * 8 + nt) * 32 + lane];
                    mma16(acc1[nt], a1[kt], wf.x, wf.y);
                    mma16(acc1[nt], a1[kt], wf.z, wf.w);
                }

            // layer2 partials over this half's 64 cols
#pragma unroll
            for (int nt = 0; nt < 8; nt++) {
                int col = half * 64 + nt * 8 + 2 * tg;
                float2 bv = *(const float2*)(s_b1 + col);
                float h00 = fmaxf(acc1[nt][0] + bv.x, 0.0f);
                float h01 = fmaxf(acc1[nt][1] + bv.y, 0.0f);
                float h10 = fmaxf(acc1[nt][2] + bv.x, 0.0f);
                float h11 = fmaxf(acc1[nt][3] + bv.y, 0.0f);
                float4 wv0 = *(const float4*)(s_w2t + col * 4);
                float4 wv1 = *(const float4*)(s_w2t + (col + 1) * 4);
                p0[0] = fmaf(h00, wv0.x, fmaf(h01, wv1.x, p0[0]));
                p0[1] = fmaf(h00, wv0.y, fmaf(h01, wv1.y, p0[1]));
                p0[2] = fmaf(h00, wv0.z, fmaf(h01, wv1.z, p0[2]));
                p0[3] = fmaf(h00, wv0.w, fmaf(h01, wv1.w, p0[3]));
                p1[0] = fmaf(h10, wv0.x, fmaf(h11, wv1.x, p1[0]));
                p1[1] = fmaf(h10, wv0.y, fmaf(h11, wv1.y, p1[1]));
                p1[2] = fmaf(h10, wv0.z, fmaf(h11, wv1.z, p1[2]));
                p1[3] = fmaf(h10, wv0.w, fmaf(h11, wv1.w, p1[3]));
            }
        }

        // ---- quad reduce (tg dimension), bias, relu, permute, store ----
#pragma unroll
        for (int off = 1; off <= 2; off <<= 1) {
#pragma unroll
            for (int q = 0; q < 4; q++) {
                p0[q] += __shfl_xor_sync(0xffffffffu, p0[q], off);
                p1[q] += __shfl_xor_sync(0xffffffffu, p1[q], off);
            }
        }
        if (tg == 0) {
            float o0 = fmaxf(s_b2[0] + p0[0], 0.0f);
            float o1 = fmaxf(s_b2[1] + p0[1], 0.0f);
            float o2 = fmaxf(s_b2[2] + p0[2], 0.0f);
            float o3 = fmaxf(s_b2[3] + p0[3], 0.0f);
            // raw = concat(net[...,1:4], net[...,0:1])
            ((float4*)out)[r0] = make_float4(o1, o2, o3, o0);
            o0 = fmaxf(s_b2[0] + p1[0], 0.0f);
            o1 = fmaxf(s_b2[1] + p1[1], 0.0f);
            o2 = fmaxf(s_b2[2] + p1[2], 0.0f);
            o3 = fmaxf(s_b2[3] + p1[3], 0.0f);
            ((float4*)out)[r0 + 8] = make_float4(o1, o2, o3, o0);
        }
    }
}

// ---------------------------------------------------------------------------
extern "C" void kernel_launch(void* const* d_in, const int* in_sizes, int n_in,
                              void* d_out, int out_size) {
    const float* coords = (const float*)d_in[0];
    const float* tri    = (const float*)d_in[1];
    const float* w0     = (const float*)d_in[2];
    const float* b0     = (const float*)d_in[3];
    const float* w1     = (const float*)d_in[4];
    const float* b1     = (const float*)d_in[5];
    const float* w2     = (const float*)d_in[6];
    const float* b2     = (const float*)d_in[7];
    float* out = (float*)d_out;

    int total = in_sizes[0] / 3;   // B * N points = MLP rows

    transpose_kernel<<<(3 * HH * WW + 127) / 128, 128>>>(tri);
    sample_kernel<<<total / 32, 256>>>(coords);

    int mlp_smem = SMEM_U32 * 4;   // ~85 KB dynamic shared
    cudaFuncSetAttribute(mlp_kernel,
                         cudaFuncAttributeMaxDynamicSharedMemorySize, mlp_smem);
    mlp_kernel<<<148, 512, mlp_smem>>>(w0, b0, w1, b1, w2, b2, out, total);
}

// round 17
// speedup vs baseline: 3.1963x; 1.0372x over previous
#include <cuda_runtime.h>
#include <cuda_fp16.h>
#include <cstdint>

#define CCH 32
#define HH 128
#define WW 128
#define NPTS 262144

// fp16 triplanes, (plane, y, x, c) with 32 fp16 per texel = 64B lines; 3 MB.
__device__ uint4 g_tph[3 * HH * WW * 4];

// ---------------------------------------------------------------------------
// fp16 helpers + mma.sync m16n8k16
// ---------------------------------------------------------------------------
__device__ __forceinline__ void mma16(float* d, const uint32_t* a,
                                      uint32_t b0, uint32_t b1) {
    asm volatile(
        "mma.sync.aligned.m16n8k16.row.col.f32.f16.f16.f32 "
        "{%0,%1,%2,%3}, {%4,%5,%6,%7}, {%8,%9}, {%0,%1,%2,%3};"
        : "+f"(d[0]), "+f"(d[1]), "+f"(d[2]), "+f"(d[3])
        : "r"(a[0]), "r"(a[1]), "r"(a[2]), "r"(a[3]), "r"(b0), "r"(b1));
}
__device__ __forceinline__ uint32_t pack_f16(float v0, float v1) {
    __half2 h = __floats2half2_rn(v0, v1);
    return *(uint32_t*)&h;
}
__device__ __forceinline__ void split_pack_f16(float v0, float v1,
                                               uint32_t& hi, uint32_t& lo) {
    __half2 h = __floats2half2_rn(v0, v1);
    float2 hf = __half22float2(h);
    __half2 l = __floats2half2_rn(v0 - hf.x, v1 - hf.y);
    hi = *(uint32_t*)&h;
    lo = *(uint32_t*)&l;
}

// ---------------------------------------------------------------------------
// K1: transpose (3*C, H, W) fp32 -> (3, H, W, C) fp16
// ---------------------------------------------------------------------------
__global__ void transpose_kernel(const float* __restrict__ tri) {
    int t = blockIdx.x * blockDim.x + threadIdx.x;
    if (t >= 3 * HH * WW) return;
    int p  = t / (HH * WW);
    int yx = t - p * (HH * WW);
    const float* src = tri + (size_t)p * CCH * HH * WW + yx;
    uint32_t v[16];
#pragma unroll
    for (int c = 0; c < 16; c++)
        v[c] = pack_f16(src[(size_t)(2*c) * HH * WW],
                        src[(size_t)(2*c+1) * HH * WW]);
    uint4* dst = g_tph + (size_t)t * 4;
#pragma unroll
    for (int q = 0; q < 4; q++)
        dst[q] = make_uint4(v[4*q], v[4*q+1], v[4*q+2], v[4*q+3]);
}

// ---------------------------------------------------------------------------
// fp16 bilinear sample of one plane, 8-channel slice s (s = 0..3)
// ---------------------------------------------------------------------------
__device__ __forceinline__ void sample_plane_h(const uint4* __restrict__ plane,
                                               float gx, float gy, int s,
                                               float* acc) {
    float x = (gx + 1.0f) * 0.5f * (WW - 1);
    float y = (gy + 1.0f) * 0.5f * (HH - 1);
    float x0f = floorf(x), y0f = floorf(y);
    float wx = x - x0f,   wy = y - y0f;
    int x0 = (int)x0f, y0 = (int)y0f;
    int x1 = x0 + 1,   y1 = y0 + 1;

    float vxa = (x0 >= 0 && x0 < WW) ? 1.0f : 0.0f;
    float vxb = (x1 >= 0 && x1 < WW) ? 1.0f : 0.0f;
    float vya = (y0 >= 0 && y0 < HH) ? 1.0f : 0.0f;
    float vyb = (y1 >= 0 && y1 < HH) ? 1.0f : 0.0f;

    int xa = min(max(x0, 0), WW - 1);
    int xb = min(max(x1, 0), WW - 1);
    int ya = min(max(y0, 0), HH - 1);
    int yb = min(max(y1, 0), HH - 1);

    float wxs[2] = {(1.0f - wx) * vxa, wx * vxb};
    float wys[2] = {(1.0f - wy) * vya, wy * vyb};
    int   xi[2]  = {xa, xb};
    int   yi[2]  = {ya, yb};

#pragma unroll
    for (int cy = 0; cy < 2; cy++) {
#pragma unroll
        for (int cx = 0; cx < 2; cx++) {
            float w = wxs[cx] * wys[cy];
            uint4 v = __ldg(plane + (size_t)(yi[cy] * WW + xi[cx]) * 4 + s);
            float2 f0 = __half22float2(*(__half2*)&v.x);
            float2 f1 = __half22float2(*(__half2*)&v.y);
            float2 f2 = __half22float2(*(__half2*)&v.z);
            float2 f3 = __half22float2(*(__half2*)&v.w);
            acc[0] = fmaf(w, f0.x, acc[0]);
            acc[1] = fmaf(w, f0.y, acc[1]);
            acc[2] = fmaf(w, f1.x, acc[2]);
            acc[3] = fmaf(w, f1.y, acc[3]);
            acc[4] = fmaf(w, f2.x, acc[4]);
            acc[5] = fmaf(w, f2.y, acc[5]);
            acc[6] = fmaf(w, f3.x, acc[6]);
            acc[7] = fmaf(w, f3.y, acc[7]);
        }
    }
}

// ---------------------------------------------------------------------------
// K2 (fused): sample 512 positions -> smem feats -> warp-local MLP.
// Block = 512 positions of one batch = 512 MLP rows (32 ch x 16 rows).
// Row mapping: r = b*NPTS + c*8192 + pblk*16 + i ; feats[r][k] = st[c][i*32+k].
// st swizzle: idx = c*529 + pos + (pos>>5)  (stores conflict-free, verified).
// ---------------------------------------------------------------------------
#define ST_STRIDE 529
// smem uint32 offsets
#define OFF_W1F 0          // 16384 (uint4 {bh0,bh1,bl0,bl1} per lane)
#define OFF_W0F 16384      // 4096
#define OFF_W2T 20480      // 512 floats
#define OFF_B0  20992      // 128
#define OFF_B1  21120      // 128
#define OFF_B2  21248      // 16
#define OFF_ST  21264      // 32*529 = 16928 floats
#define SMEM_U32 38192     // ~153 KB

__global__ void __launch_bounds__(512)
fused_kernel(const float* __restrict__ coords,
             const float* __restrict__ w0, const float* __restrict__ b0,
             const float* __restrict__ w1, const float* __restrict__ b1,
             const float* __restrict__ w2, const float* __restrict__ b2,
             float* __restrict__ out, int total) {
    extern __shared__ uint32_t smem[];
    uint4* s_w1f = (uint4*)(smem + OFF_W1F);
    uint4* s_w0f = (uint4*)(smem + OFF_W0F);
    float* s_w2t = (float*)(smem + OFF_W2T);
    float* s_b0  = (float*)(smem + OFF_B0);
    float* s_b1  = (float*)(smem + OFF_B1);
    float* s_b2  = (float*)(smem + OFF_B2);
    float* s_st  = (float*)(smem + OFF_ST);

    int tid = threadIdx.x;

    // ---- pack w1 fragments: bt = kt*16+nt (kt 0..7) ----
    for (int i = tid; i < 4096; i += 512) {
        int bt = i >> 5, li = i & 31;
        int kt = bt >> 4, nt = bt & 15;
        int gg = li >> 2, tq = li & 3;
        int n  = nt * 8 + gg;
        int k0 = kt * 16 + 2 * tq;
        uint32_t h0p, l0p, h1p, l1p;
        split_pack_f16(w1[n * 128 + k0],     w1[n * 128 + k0 + 1], h0p, l0p);
        split_pack_f16(w1[n * 128 + k0 + 8], w1[n * 128 + k0 + 9], h1p, l1p);
        s_w1f[i] = make_uint4(h0p, h1p, l0p, l1p);
    }
    // ---- pack w0 fragments: bt = kt*16+nt (kt 0..1) ----
    for (int i = tid; i < 1024; i += 512) {
        int bt = i >> 5, li = i & 31;
        int kt = bt >> 4, nt = bt & 15;
        int gg = li >> 2, tq = li & 3;
        int n  = nt * 8 + gg;
        int k0 = kt * 16 + 2 * tq;
        uint32_t h0p, l0p, h1p, l1p;
        split_pack_f16(w0[n * 32 + k0],     w0[n * 32 + k0 + 1], h0p, l0p);
        split_pack_f16(w0[n * 32 + k0 + 8], w0[n * 32 + k0 + 9], h1p, l1p);
        s_w0f[i] = make_uint4(h0p, h1p, l0p, l1p);
    }
    if (tid < 512) s_w2t[tid] = w2[(tid & 3) * 128 + (tid >> 2)];
    if (tid < 128) { s_b0[tid] = b0[tid]; s_b1[tid] = b1[tid]; }
    if (tid < 4)   s_b2[tid] = b2[tid];
    __syncthreads();

    int lane = tid & 31;
    int wid  = tid >> 5;
    int g    = lane >> 2;
    int tg   = lane & 3;
    int s    = tid & 3;          // sampler channel slice (8 ch)

    int nblocks = total >> 9;    // 512 rows per block
    for (int blk = blockIdx.x; blk < nblocks; blk += gridDim.x) {
        int b    = blk >> 9;     // 512 blocks per batch
        int pblk = blk & 511;

        // ---- sample 512 points (4 thr/pt, 4 passes) ----
#pragma unroll 1
        for (int pass = 0; pass < 4; pass++) {
            int pLocal = (tid >> 2) + pass * 128;
            int p = b * NPTS + pblk * 512 + pLocal;
            float gx = __ldg(coords + 3 * p + 0);
            float gy = __ldg(coords + 3 * p + 1);
            float gz = __ldg(coords + 3 * p + 2);

            float acc[8];
#pragma unroll
            for (int j = 0; j < 8; j++) acc[j] = 0.0f;
            // split order: plane0 = feat_xy, plane1 = feat_yz, plane2 = feat_xz
            sample_plane_h(g_tph,                     gx, gy, s, acc);
            sample_plane_h(g_tph + 2 * HH * WW * 4,   gx, gz, s, acc);
            sample_plane_h(g_tph + 1 * HH * WW * 4,   gy, gz, s, acc);

            int possw = pLocal + (pLocal >> 5);
#pragma unroll
            for (int j = 0; j < 8; j++)
                s_st[(8 * s + j) * ST_STRIDE + possw] = acc[j];
        }
        __syncthreads();

        // ---- MLP: warp handles channels 2*wid and 2*wid+1 ----
#pragma unroll 1
        for (int ci = 0; ci < 2; ci++) {
            int c = 2 * wid + ci;
            const float* stc = s_st + c * ST_STRIDE;
            int rowA = 33 * g;          // swizzled row base (rows g, g+8)
            int rowB = 33 * (g + 8);

            // ---- layer0 A-frags from smem feats ----
            uint32_t a0[2][4];
#pragma unroll
            for (int kt = 0; kt < 2; kt++) {
                int k = 16 * kt + 2 * tg;
                a0[kt][0] = pack_f16(stc[rowA + k],     stc[rowA + k + 1]);
                a0[kt][1] = pack_f16(stc[rowB + k],     stc[rowB + k + 1]);
                a0[kt][2] = pack_f16(stc[rowA + k + 8], stc[rowA + k + 9]);
                a0[kt][3] = pack_f16(stc[rowB + k + 8], stc[rowB + k + 9]);
            }

            // ---- layer0 ----
            float acc0[16][4];
#pragma unroll
            for (int nt = 0; nt < 16; nt++)
#pragma unroll
                for (int q = 0; q < 4; q++) acc0[nt][q] = 0.0f;

#pragma unroll
            for (int kt = 0; kt < 2; kt++)
#pragma unroll
                for (int nt = 0; nt < 16; nt++) {
                    uint4 wf = s_w0f[(kt * 16 + nt) * 32 + lane];
                    mma16(acc0[nt], a0[kt], wf.x, wf.y);
                    mma16(acc0[nt], a0[kt], wf.z, wf.w);
                }

            // ---- epilogue0: bias+relu+pack -> layer1 A-frags ----
            uint32_t a1[8][4];
#pragma unroll
            for (int kt = 0; kt < 8; kt++) {
                float2 bA = *(const float2*)(s_b0 + 16 * kt + 2 * tg);
                float2 bB = *(const float2*)(s_b0 + 16 * kt + 2 * tg + 8);
                a1[kt][0] = pack_f16(fmaxf(acc0[2*kt][0] + bA.x, 0.0f),
                                     fmaxf(acc0[2*kt][1] + bA.y, 0.0f));
                a1[kt][1] = pack_f16(fmaxf(acc0[2*kt][2] + bA.x, 0.0f),
                                     fmaxf(acc0[2*kt][3] + bA.y, 0.0f));
                a1[kt][2] = pack_f16(fmaxf(acc0[2*kt+1][0] + bB.x, 0.0f),
                                     fmaxf(acc0[2*kt+1][1] + bB.y, 0.0f));
                a1[kt][3] = pack_f16(fmaxf(acc0[2*kt+1][2] + bB.x, 0.0f),
                                     fmaxf(acc0[2*kt+1][3] + bB.y, 0.0f));
            }

            // ---- layer1 + layer2 in two n-halves ----
            float p0[4] = {0, 0, 0, 0};
            float p1[4] = {0, 0, 0, 0};
#pragma unroll
            for (int half = 0; half < 2; half++) {
                float acc1[8][4];
#pragma unroll
                for (int nt = 0; nt < 8; nt++)
#pragma unroll
                    for (int q = 0; q < 4; q++) acc1[nt][q] = 0.0f;

#pragma unroll
                for (int kt = 0; kt < 8; kt++)
#pragma unroll
                    for (int nt = 0; nt < 8; nt++) {
                        uint4 wf = s_w1f[(kt * 16 + half * 8 + nt) * 32 + lane];
                        mma16(acc1[nt], a1[kt], wf.x, wf.y);
                        mma16(acc1[nt], a1[kt], wf.z, wf.w);
                    }

#pragma unroll
                for (int nt = 0; nt < 8; nt++) {
                    int col = half * 64 + nt * 8 + 2 * tg;
                    float2 bv = *(const float2*)(s_b1 + col);
                    float h00 = fmaxf(acc1[nt][0] + bv.x, 0.0f);
                    float h01 = fmaxf(acc1[nt][1] + bv.y, 0.0f);
                    float h10 = fmaxf(acc1[nt][2] + bv.x, 0.0f);
                    float h11 = fmaxf(acc1[nt][3] + bv.y, 0.0f);
                    float4 wv0 = *(const float4*)(s_w2t + col * 4);
                    float4 wv1 = *(const float4*)(s_w2t + (col + 1) * 4);
                    p0[0] = fmaf(h00, wv0.x, fmaf(h01, wv1.x, p0[0]));
                    p0[1] = fmaf(h00, wv0.y, fmaf(h01, wv1.y, p0[1]));
                    p0[2] = fmaf(h00, wv0.z, fmaf(h01, wv1.z, p0[2]));
                    p0[3] = fmaf(h00, wv0.w, fmaf(h01, wv1.w, p0[3]));
                    p1[0] = fmaf(h10, wv0.x, fmaf(h11, wv1.x, p1[0]));
                    p1[1] = fmaf(h10, wv0.y, fmaf(h11, wv1.y, p1[1]));
                    p1[2] = fmaf(h10, wv0.z, fmaf(h11, wv1.z, p1[2]));
                    p1[3] = fmaf(h10, wv0.w, fmaf(h11, wv1.w, p1[3]));
                }
            }

            // ---- quad reduce, bias, relu, permute, store ----
#pragma unroll
            for (int off = 1; off <= 2; off <<= 1) {
#pragma unroll
                for (int q = 0; q < 4; q++) {
                    p0[q] += __shfl_xor_sync(0xffffffffu, p0[q], off);
                    p1[q] += __shfl_xor_sync(0xffffffffu, p1[q], off);
                }
            }
            if (tg == 0) {
                int r0 = b * NPTS + c * 8192 + pblk * 16 + g;
                float o0 = fmaxf(s_b2[0] + p0[0], 0.0f);
                float o1 = fmaxf(s_b2[1] + p0[1], 0.0f);
                float o2 = fmaxf(s_b2[2] + p0[2], 0.0f);
                float o3 = fmaxf(s_b2[3] + p0[3], 0.0f);
                // raw = concat(net[...,1:4], net[...,0:1])
                ((float4*)out)[r0] = make_float4(o1, o2, o3, o0);
                o0 = fmaxf(s_b2[0] + p1[0], 0.0f);
                o1 = fmaxf(s_b2[1] + p1[1], 0.0f);
                o2 = fmaxf(s_b2[2] + p1[2], 0.0f);
                o3 = fmaxf(s_b2[3] + p1[3], 0.0f);
                ((float4*)out)[r0 + 8] = make_float4(o1, o2, o3, o0);
            }
        }
        __syncthreads();   // st consumed before next block overwrites it
    }
}

// ---------------------------------------------------------------------------
extern "C" void kernel_launch(void* const* d_in, const int* in_sizes, int n_in,
                              void* d_out, int out_size) {
    const float* coords = (const float*)d_in[0];
    const float* tri    = (const float*)d_in[1];
    const float* w0     = (const float*)d_in[2];
    const float* b0     = (const float*)d_in[3];
    const float* w1     = (const float*)d_in[4];
    const float* b1     = (const float*)d_in[5];
    const float* w2     = (const float*)d_in[6];
    const float* b2     = (const float*)d_in[7];
    float* out = (float*)d_out;

    int total = in_sizes[0] / 3;   // B * N points = MLP rows

    transpose_kernel<<<(3 * HH * WW + 127) / 128, 128>>>(tri);

    int fsmem = SMEM_U32 * 4;   // ~153 KB dynamic shared
    cudaFuncSetAttribute(fused_kernel,
                         cudaFuncAttributeMaxDynamicSharedMemorySize, fsmem);
    fused_kernel<<<148, 512, fsmem>>>(coords, w0, b0, w1, b1, w2, b2, out, total);
}